// round 12
// baseline (speedup 1.0000x reference)
#include <cuda_runtime.h>
#include <math.h>

#define BB 4
#define CCH 64
#define HH 192
#define WWD 192
#define HWSZ (HH*WWD)          // 36864
#define NPIX (BB*HWSZ)         // 147456

typedef unsigned long long u64;
typedef unsigned int u32;

// ---------------- packed helpers --------------------------------------------
__device__ __forceinline__ u64 pk2(float a, float b){
    u64 r; asm("mov.b64 %0, {%1, %2};" : "=l"(r) : "f"(a), "f"(b)); return r;
}
__device__ __forceinline__ u64 bcast2(float a){
    u64 r; asm("mov.b64 %0, {%1, %1};" : "=l"(r) : "f"(a)); return r;
}
__device__ __forceinline__ float2 upk(u64 v){
    float2 f; asm("mov.b64 {%0, %1}, %2;" : "=f"(f.x), "=f"(f.y) : "l"(v)); return f;
}
__device__ __forceinline__ void ffma2(u64 &d, u64 a, u64 b){
    asm("fma.rn.f32x2 %0, %1, %2, %0;" : "+l"(d) : "l"(a), "l"(b));
}
__device__ __forceinline__ u32 f2tf32(float v){
    u32 r; asm("cvt.rna.tf32.f32 %0, %1;" : "=r"(r) : "f"(v)); return r;
}
#define MMA_TF32(C, A0,A1,A2,A3, B0,B1) \
    asm volatile("mma.sync.aligned.m16n8k8.row.col.f32.tf32.tf32.f32 " \
        "{%0,%1,%2,%3}, {%4,%5,%6,%7}, {%8,%9}, {%0,%1,%2,%3};" \
        : "+f"(C[0]), "+f"(C[1]), "+f"(C[2]), "+f"(C[3]) \
        : "r"(A0), "r"(A1), "r"(A2), "r"(A3), "r"(B0), "r"(B1))

// ---------------- scratch (device globals) ----------------------------------
__device__ float g_off  [BB*18*HWSZ];
__device__ float g_mask [BB*9 *HWSZ];
__device__ float g_xd   [BB*CCH*HWSZ];
__device__ float g_xa   [BB*CCH*HWSZ];
__device__ u32   g_xatf [BB*CCH*HWSZ];   // tf32 bits of xa
__device__ u32   g_xtf  [BB*CCH*HWSZ];   // tf32 bits of x
__device__ u32   g_ds   [(size_t)BB*576*HWSZ];  // sampled deform planes, tf32 bits [b][tap*64+c][hw]
__device__ float g_r1   [BB*256*HWSZ];   // tf32-rounded bit patterns (as float)
__device__ float g_xr   [BB*CCH*HWSZ];
__device__ float g_n1   [BB*32*HWSZ];
__device__ float g_n2   [BB*32*HWSZ];
__device__ float g_camean[BB*CCH];
__device__ float g_ca   [BB*CCH];

// tf32 weights in per-chunk staging order
__device__ u32   g_wofftf[8*2304];    // [cc(8)][tap(9)][kc(8)][o(32 pad)]
__device__ u32   g_wdctf2[576*64];    // [k=tap*64+c][o]
__device__ u32   g_wr1tf [4*4096];    // [ocq(4)][cc(8)][kc(8)][o(64)]
__device__ u32   g_wr2Tf [32*4608];   // [cc(32)][tap(9)][kc(8)][o(64)]
__device__ float g_wn1T  [64*32];     // [c][o]
__device__ float g_wn3T  [32*64];     // [c][o]

__device__ __forceinline__ float leakyf(float v){ return v >= 0.f ? v : 0.1f*v; }
__device__ __forceinline__ float sigmf(float v){ return 1.f/(1.f+__expf(-v)); }

// ---------------- weight prep -----------------------------------------------
__global__ void k_prep(const float* __restrict__ w_off, const float* __restrict__ w_dc,
                       const float* __restrict__ w_r1,  const float* __restrict__ w_r2,
                       const float* __restrict__ w_n1,  const float* __restrict__ w_n3){
    int t = blockIdx.x*blockDim.x + threadIdx.x;
    int nt = gridDim.x*blockDim.x;
    for (int i=t;i<8*2304;i+=nt){
        int cc=i/2304, rem=i%2304, tap=rem>>8, kc=(rem>>5)&7, o=rem&31;
        g_wofftf[i] = (o<27) ? f2tf32(w_off[(o*64 + cc*8+kc)*9 + tap]) : 0u;
    }
    for (int i=t;i<576*64;i+=nt){
        int k=i>>6, o=i&63, c=k&63, tap=k>>6;
        g_wdctf2[i] = f2tf32(w_dc[(o*64+c)*9+tap]);
    }
    for (int i=t;i<4*4096;i+=nt){
        int q=i>>12, rem=i&4095, cc=rem>>9, kc=(rem>>6)&7, o=rem&63;
        g_wr1tf[i] = f2tf32(w_r1[(q*64+o)*64 + cc*8+kc]);
    }
    for (int i=t;i<32*4608;i+=nt){
        int cc=i/4608, rem=i%4608, tap=rem>>9, kc=(rem>>6)&7, o=rem&63;
        g_wr2Tf[i] = f2tf32(w_r2[(o*256 + cc*8 + kc)*9 + tap]);
    }
    for (int i=t;i<64*32;i+=nt){ int o=i%32; int c=i/32; g_wn1T[i]=w_n1[o*64+c]; }
    for (int i=t;i<32*64;i+=nt){ int o=i%64; int c=i/64; g_wn3T[i]=w_n3[o*32+c]; }
}

// ---------------- x -> tf32 bits copy (full grid-stride coverage) ------------
__global__ void k_cvtx(const float* __restrict__ x){
    int nt = gridDim.x*blockDim.x;
    const float4* src = (const float4*)x;
    uint4* dst = (uint4*)g_xtf;
    const int NV = BB*CCH*HWSZ/4;          // 2,359,296 uint4
    for (int i = blockIdx.x*blockDim.x + threadIdx.x; i < NV; i += nt){
        float4 v = src[i];
        dst[i] = make_uint4(f2tf32(v.x), f2tf32(v.y), f2tf32(v.z), f2tf32(v.w));
    }
}

// ---------------- offset conv 3x3 64->27 via MMA -----------------------------
#define ASX 200
#define BSO 40
__global__ __launch_bounds__(128,4) void k_off_mma(const float* __restrict__ b_off){
    __shared__ __align__(16) u32 As[3*8*ASX];   // [ri][kc][200]
    __shared__ __align__(16) u32 Bs[9*8*BSO];   // [tap][kc][40]
    int blk = blockIdx.x;
    int b = blk / HH, r = blk % HH;
    int tid = threadIdx.x;
    int wm = tid >> 5, lane = tid & 31;
    int lg = lane >> 2, lt = lane & 3;

    float c[3][4][4];
    #pragma unroll
    for (int mf=0;mf<3;mf++)
        #pragma unroll
        for (int nf=0;nf<4;nf++)
            #pragma unroll
            for (int q=0;q<4;q++) c[mf][nf][q]=0.f;

    for (int cc=0; cc<8; cc++){
        if (tid < 48){ int rc = tid>>1, side = tid&1;
            As[rc*ASX + 3 + side*193] = 0u; }
        #pragma unroll
        for (int j=0;j<9;j++){
            int i = tid + 128*j;                  // < 1152
            int rc = i/48, q = i - rc*48;
            int ri = rc>>3, kc = rc&7;
            int gr = r - 1 + ri;
            uint4 v = make_uint4(0u,0u,0u,0u);
            if (gr>=0 && gr<HH)
                v = *(const uint4*)(&g_xtf[((size_t)(b*64 + cc*8 + kc))*HWSZ + gr*WWD + 4*q]);
            *(uint4*)&As[rc*ASX + 4 + 4*q] = v;
        }
        #pragma unroll
        for (int j=0;j<5;j++){
            int i = tid + 128*j;
            if (i < 576){
                int wd = 4*i;
                int tap = wd>>8, rem = wd&255, kc = rem>>5, o = rem&31;
                *(uint4*)&Bs[(tap*8+kc)*BSO + o] = *(const uint4*)&g_wofftf[cc*2304 + wd];
            }
        }
        __syncthreads();
        #pragma unroll
        for (int tap=0; tap<9; tap++){
            int dh = tap/3, dw = tap%3;
            u32 a[3][4];
            #pragma unroll
            for (int mf=0;mf<3;mf++){
                int p0 = wm*48 + mf*16 + lg;
                int col0 = p0 + dw + 3;
                const u32* alo = &As[(dh*8+lt  )*ASX];
                const u32* ahi = &As[(dh*8+lt+4)*ASX];
                a[mf][0]=alo[col0]; a[mf][1]=alo[col0+8];
                a[mf][2]=ahi[col0]; a[mf][3]=ahi[col0+8];
            }
            u32 bb[4][2];
            #pragma unroll
            for (int nf=0;nf<4;nf++){
                int n = nf*8 + lg;
                bb[nf][0] = Bs[(tap*8+lt  )*BSO + n];
                bb[nf][1] = Bs[(tap*8+lt+4)*BSO + n];
            }
            #pragma unroll
            for (int mf=0;mf<3;mf++)
                #pragma unroll
                for (int nf=0;nf<4;nf++)
                    MMA_TF32(c[mf][nf], a[mf][0],a[mf][1],a[mf][2],a[mf][3], bb[nf][0],bb[nf][1]);
        }
        __syncthreads();
    }
    int rbase = r*WWD;
    #pragma unroll
    for (int mf=0;mf<3;mf++){
        int p0 = wm*48 + mf*16 + lg;
        #pragma unroll
        for (int nf=0;nf<4;nf++){
            int o0 = nf*8 + 2*lt;
            #pragma unroll
            for (int q=0;q<4;q++){
                int o = o0 + (q&1);
                int p = p0 + (q>>1)*8;
                if (o < 27){
                    float v = leakyf(c[mf][nf][q] + b_off[o]);
                    if (o < 18) g_off [(b*18+o)*HWSZ + rbase + p] = v;
                    else        g_mask[(b*9+(o-18))*HWSZ + rbase + p] = sigmf(v);
                }
            }
        }
    }
}

// ---------------- deform sampler: high-occupancy bilinear gather -------------
// grid = (HH, 9) for ONE batch b0; 192 threads (one per px).
__global__ __launch_bounds__(192,8) void k_dsample(const float* __restrict__ x, int b0){
    int b = b0, r = blockIdx.x;
    int tap = blockIdx.y;
    int px = threadIdx.x;
    int hw = r*WWD + px;

    float dy = g_off[(b*18+2*tap  )*HWSZ+hw];
    float dx = g_off[(b*18+2*tap+1)*HWSZ+hw];
    float m  = g_mask[(b*9+tap)*HWSZ+hw];
    float py = (float)r  + (float)(tap/3-1) + dy;
    float pxf= (float)px + (float)(tap%3-1) + dx;
    float y0f = floorf(py), x0f = floorf(pxf);
    float wy = py - y0f,  wx = pxf - x0f;
    int y0=(int)y0f, x0=(int)x0f, y1=y0+1, x1=x0+1;
    bool vy0=(y0>=0&&y0<HH), vy1=(y1>=0&&y1<HH);
    bool vx0=(x0>=0&&x0<WWD), vx1=(x1>=0&&x1<WWD);
    float w00=(1.f-wy)*(1.f-wx)*((vy0&&vx0)?m:0.f);
    float w01=(1.f-wy)*wx      *((vy0&&vx1)?m:0.f);
    float w10=wy*(1.f-wx)      *((vy1&&vx0)?m:0.f);
    float w11=wy*wx            *((vy1&&vx1)?m:0.f);
    int cy0=min(max(y0,0),HH-1), cy1=min(max(y1,0),HH-1);
    int cx0=min(max(x0,0),WWD-1), cx1=min(max(x1,0),WWD-1);
    int i00=cy0*WWD+cx0, i01=cy0*WWD+cx1, i10=cy1*WWD+cx0, i11=cy1*WWD+cx1;

    const float* xb = x + (size_t)b*64*HWSZ;
    u32* dst = g_ds + (size_t)(b*576 + tap*64)*HWSZ + hw;
    #pragma unroll 8
    for (int c=0;c<64;c++){
        const float* xc = xb + (size_t)c*HWSZ;
        float v = w00*xc[i00] + w01*xc[i01] + w10*xc[i10] + w11*xc[i11];
        dst[(size_t)c*HWSZ] = f2tf32(v);
    }
}

// ---------------- dc GEMM: 576 -> 64 over sampled planes (one batch) ---------
__global__ __launch_bounds__(256,2) void k_dc_gemm(const float* __restrict__ b_dc, int b0){
    __shared__ __align__(16) u32 As[16*ASX];    // 12.8KB
    __shared__ __align__(16) u32 Bs[16*72];     // 4.6KB
    int b = b0, r = blockIdx.x;
    int tid = threadIdx.x;
    int w  = tid >> 5, lane = tid & 31;
    int wm = w & 3, wn = w >> 2;
    int lg = lane >> 2, lt = lane & 3;

    float c[3][4][4];
    #pragma unroll
    for (int mf=0;mf<3;mf++)
        #pragma unroll
        for (int nf=0;nf<4;nf++)
            #pragma unroll
            for (int q=0;q<4;q++) c[mf][nf][q]=0.f;

    const u32* dsb = g_ds + (size_t)b*576*HWSZ + r*WWD;

    for (int ch=0; ch<36; ch++){
        #pragma unroll
        for (int j=0;j<3;j++){
            int i = tid + 256*j;                  // < 768
            int kc = i/48, q = i - kc*48;
            *(uint4*)&As[kc*ASX + 4*q] =
                *(const uint4*)&dsb[(size_t)(ch*16 + kc)*HWSZ + 4*q];
        }
        {
            int wd = 4*tid;                       // < 1024
            int kc = wd>>6, o = wd&63;
            *(uint4*)&Bs[kc*72 + o] = *(const uint4*)&g_wdctf2[ch*1024 + wd];
        }
        __syncthreads();
        #pragma unroll
        for (int ks=0; ks<2; ks++){
            u32 a[3][4];
            #pragma unroll
            for (int mf=0;mf<3;mf++){
                int p0 = wm*48 + mf*16 + lg;
                const u32* alo = &As[(ks*8+lt  )*ASX];
                const u32* ahi = &As[(ks*8+lt+4)*ASX];
                a[mf][0]=alo[p0]; a[mf][1]=alo[p0+8];
                a[mf][2]=ahi[p0]; a[mf][3]=ahi[p0+8];
            }
            u32 bb[4][2];
            #pragma unroll
            for (int nf=0;nf<4;nf++){
                int n = wn*32 + nf*8 + lg;
                bb[nf][0] = Bs[(ks*8+lt  )*72 + n];
                bb[nf][1] = Bs[(ks*8+lt+4)*72 + n];
            }
            #pragma unroll
            for (int mf=0;mf<3;mf++)
                #pragma unroll
                for (int nf=0;nf<4;nf++)
                    MMA_TF32(c[mf][nf], a[mf][0],a[mf][1],a[mf][2],a[mf][3], bb[nf][0],bb[nf][1]);
        }
        __syncthreads();
    }
    float* xdb = g_xd + (size_t)b*64*HWSZ + r*WWD;
    #pragma unroll
    for (int mf=0;mf<3;mf++){
        int p0 = wm*48 + mf*16 + lg;
        #pragma unroll
        for (int nf=0;nf<4;nf++){
            int o0 = wn*32 + nf*8 + 2*lt;
            float bz0 = b_dc[o0], bz1 = b_dc[o0+1];
            xdb[(size_t)o0    *HWSZ + p0    ] = c[mf][nf][0] + bz0;
            xdb[(size_t)(o0+1)*HWSZ + p0    ] = c[mf][nf][1] + bz1;
            xdb[(size_t)o0    *HWSZ + p0 + 8] = c[mf][nf][2] + bz0;
            xdb[(size_t)(o0+1)*HWSZ + p0 + 8] = c[mf][nf][3] + bz1;
        }
    }
}

// ---------------- channel-attention mean reduce ------------------------------
__global__ void k_ca_red(){
    int bc = blockIdx.x;
    const float4* src = (const float4*)(g_xd + (size_t)bc*HWSZ);
    float s = 0.f;
    for (int i=threadIdx.x;i<HWSZ/4;i+=blockDim.x){
        float4 v = src[i]; s += (v.x+v.y)+(v.z+v.w);
    }
    __shared__ float red[256];
    red[threadIdx.x]=s; __syncthreads();
    for (int st=128;st>0;st>>=1){ if (threadIdx.x<st) red[threadIdx.x]+=red[threadIdx.x+st]; __syncthreads(); }
    if (threadIdx.x==0) g_camean[bc] = red[0]*(1.f/(float)HWSZ);
}

// ---------------- channel-attention MLP --------------------------------------
__global__ void k_ca_mlp(const float* __restrict__ w_ca1, const float* __restrict__ b_ca1,
                         const float* __restrict__ w_ca2, const float* __restrict__ b_ca2){
    __shared__ float hid[4*8];
    int t = threadIdx.x;
    if (t<32){ int b=t/8, j=t%8;
        float s = b_ca1[j];
        for (int c=0;c<64;c++) s += w_ca1[j*64+c]*g_camean[b*64+c];
        hid[b*8+j] = fmaxf(s,0.f);
    }
    __syncthreads();
    if (t<256){ int b=t/64, o=t%64;
        float s = b_ca2[o];
        #pragma unroll
        for (int j=0;j<8;j++) s += w_ca2[o*8+j]*hid[b*8+j];
        g_ca[t] = sigmf(s);
    }
}

// ---------------- spatial attention + xa = xd*(ca+sa); also tf32 copy --------
__global__ void k_sa_xa(const float* __restrict__ w_sa, const float* __restrict__ b_sa){
    __shared__ float sW[64*9];
    for (int j=threadIdx.x;j<576;j+=blockDim.x) sW[j]=w_sa[j];
    __syncthreads();
    int p = blockIdx.x*blockDim.x + threadIdx.x;
    if (p>=NPIX) return;
    int b=p/HWSZ, hw=p%HWSZ, h=hw/WWD, w=hw%WWD;
    int toff[9]; bool tv[9];
    #pragma unroll
    for (int k=0;k<9;k++){
        int hy=h+k/3-1, wx=w+k%3-1;
        tv[k]=(hy>=0&&hy<HH&&wx>=0&&wx<WWD);
        toff[k]=tv[k]?hy*WWD+wx:0;
    }
    float s = b_sa[0];
    const float* xb = g_xd + b*64*HWSZ;
    for (int c=0;c<64;c++){
        const float* xc = xb + c*HWSZ;
        #pragma unroll
        for (int k=0;k<9;k++) if (tv[k]) s += xc[toff[k]]*sW[c*9+k];
    }
    s = sigmf(s);
    for (int c=0;c<64;c++){
        float scale = g_ca[b*64+c] + s;
        float v = xb[c*HWSZ+hw]*scale;
        g_xa  [(b*64+c)*HWSZ+hw] = v;
        g_xatf[(size_t)(b*64+c)*HWSZ+hw] = f2tf32(v);
    }
}

// ---------------- r1: conv1x1 64->256 via MMA (2-batch chunk) ----------------
__global__ __launch_bounds__(256,2) void k_r1_mma(const float* __restrict__ b_r1, int b0){
    __shared__ __align__(16) u32 As[8*ASX];     // 6.4KB
    __shared__ __align__(16) u32 Bs[8*72];      // 2.3KB
    int blk = blockIdx.x;
    int b = b0 + blk / HH, r = blk % HH;
    int oc0 = blockIdx.y*64;
    int tid = threadIdx.x;
    int w  = tid >> 5, lane = tid & 31;
    int wm = w & 3, wn = w >> 2;
    int lg = lane >> 2, lt = lane & 3;

    float c[3][4][4];
    #pragma unroll
    for (int mf=0;mf<3;mf++)
        #pragma unroll
        for (int nf=0;nf<4;nf++)
            #pragma unroll
            for (int q=0;q<4;q++) c[mf][nf][q]=0.f;

    for (int cc=0; cc<8; cc++){
        #pragma unroll
        for (int j=0;j<2;j++){
            int i = tid + 256*j;
            if (i < 384){
                int kc = i/48, q = i - kc*48;
                *(uint4*)&As[kc*ASX + 4*q] =
                    *(const uint4*)&g_xatf[((size_t)(b*64 + cc*8 + kc))*HWSZ + r*WWD + 4*q];
            }
        }
        if (tid < 128){
            int wd = 4*tid;
            int kc = wd>>6, o = wd&63;
            *(uint4*)&Bs[kc*72 + o] = *(const uint4*)&g_wr1tf[blockIdx.y*4096 + cc*512 + wd];
        }
        __syncthreads();
        u32 a[3][4];
        #pragma unroll
        for (int mf=0;mf<3;mf++){
            int p0 = wm*48 + mf*16 + lg;
            const u32* alo = &As[lt*ASX];
            const u32* ahi = &As[(lt+4)*ASX];
            a[mf][0]=alo[p0]; a[mf][1]=alo[p0+8];
            a[mf][2]=ahi[p0]; a[mf][3]=ahi[p0+8];
        }
        u32 bb[4][2];
        #pragma unroll
        for (int nf=0;nf<4;nf++){
            int n = wn*32 + nf*8 + lg;
            bb[nf][0] = Bs[lt*72 + n];
            bb[nf][1] = Bs[(lt+4)*72 + n];
        }
        #pragma unroll
        for (int mf=0;mf<3;mf++)
            #pragma unroll
            for (int nf=0;nf<4;nf++)
                MMA_TF32(c[mf][nf], a[mf][0],a[mf][1],a[mf][2],a[mf][3], bb[nf][0],bb[nf][1]);
        __syncthreads();
    }
    float* ob = g_r1 + ((size_t)b*256+oc0)*HWSZ + r*WWD;
    #pragma unroll
    for (int mf=0;mf<3;mf++){
        int p0 = wm*48 + mf*16 + lg;
        #pragma unroll
        for (int nf=0;nf<4;nf++){
            int o0 = wn*32 + nf*8 + 2*lt;
            float bz0 = b_r1[oc0+o0], bz1 = b_r1[oc0+o0+1];
            ob[(size_t)o0    *HWSZ + p0    ] = __uint_as_float(f2tf32(leakyf(c[mf][nf][0] + bz0)));
            ob[(size_t)(o0+1)*HWSZ + p0    ] = __uint_as_float(f2tf32(leakyf(c[mf][nf][1] + bz1)));
            ob[(size_t)o0    *HWSZ + p0 + 8] = __uint_as_float(f2tf32(leakyf(c[mf][nf][2] + bz0)));
            ob[(size_t)(o0+1)*HWSZ + p0 + 8] = __uint_as_float(f2tf32(leakyf(c[mf][nf][3] + bz1)));
        }
    }
}

// ---------------- r2: conv3x3 256->64 via MMA (2-batch chunk) ----------------
#define AS2 200
#define BS2 72
__global__ __launch_bounds__(256,2) void k_r2_mma(const float* __restrict__ b_r2, int b0){
    __shared__ __align__(16) u32 As[3*8*AS2];
    __shared__ __align__(16) u32 Bs[9*8*BS2];
    int blk = blockIdx.x;
    int b = b0 + blk / HH, r = blk % HH;
    int tid = threadIdx.x;
    int w  = tid >> 5, lane = tid & 31;
    int wm = w & 3, wn = w >> 2;
    int lg = lane >> 2, lt = lane & 3;

    float c[3][4][4];
    #pragma unroll
    for (int mf=0;mf<3;mf++)
        #pragma unroll
        for (int nf=0;nf<4;nf++)
            #pragma unroll
            for (int q=0;q<4;q++) c[mf][nf][q]=0.f;

    for (int cc=0; cc<32; cc++){
        if (tid < 48){ int rc = tid>>1, side = tid&1;
            As[rc*AS2 + 3 + side*193] = 0u; }
        #pragma unroll
        for (int j=0;j<5;j++){
            int i = tid + 256*j;
            if (i < 1152){
                int rc = i/48, q = i - rc*48;
                int ri = rc>>3, kc = rc&7;
                int gr = r - 1 + ri;
                uint4 v = make_uint4(0u,0u,0u,0u);
                if (gr>=0 && gr<HH)
                    v = *(const uint4*)(&g_r1[((size_t)(b*256 + cc*8 + kc))*HWSZ + gr*WWD + 4*q]);
                *(uint4*)&As[rc*AS2 + 4 + 4*q] = v;
            }
        }
        #pragma unroll
        for (int j=0;j<5;j++){
            int i = tid + 256*j;
            if (i < 1152){
                int wd = 4*i;
                int tap = wd>>9, rem = wd&511, kc = rem>>6, o = rem&63;
                *(uint4*)&Bs[(tap*8+kc)*BS2 + o] = *(const uint4*)&g_wr2Tf[cc*4608 + wd];
            }
        }
        __syncthreads();
        #pragma unroll
        for (int tap=0; tap<9; tap++){
            int dh = tap/3, dw = tap%3;
            u32 a[3][4];
            #pragma unroll
            for (int mf=0;mf<3;mf++){
                int p0 = wm*48 + mf*16 + lg;
                int col0 = p0 + dw + 3;
                const u32* alo = &As[(dh*8+lt  )*AS2];
                const u32* ahi = &As[(dh*8+lt+4)*AS2];
                a[mf][0]=alo[col0]; a[mf][1]=alo[col0+8];
                a[mf][2]=ahi[col0]; a[mf][3]=ahi[col0+8];
            }
            u32 bb[4][2];
            #pragma unroll
            for (int nf=0;nf<4;nf++){
                int n = wn*32 + nf*8 + lg;
                bb[nf][0] = Bs[(tap*8+lt  )*BS2 + n];
                bb[nf][1] = Bs[(tap*8+lt+4)*BS2 + n];
            }
            #pragma unroll
            for (int mf=0;mf<3;mf++)
                #pragma unroll
                for (int nf=0;nf<4;nf++)
                    MMA_TF32(c[mf][nf], a[mf][0],a[mf][1],a[mf][2],a[mf][3], bb[nf][0],bb[nf][1]);
        }
        __syncthreads();
    }
    float* xrb = g_xr + (size_t)b*64*HWSZ + r*WWD;
    #pragma unroll
    for (int mf=0;mf<3;mf++){
        int p0 = wm*48 + mf*16 + lg;
        #pragma unroll
        for (int nf=0;nf<4;nf++){
            int o0 = wn*32 + nf*8 + 2*lt;
            float bz0 = b_r2[o0], bz1 = b_r2[o0+1];
            xrb[(size_t)o0    *HWSZ + p0    ] = c[mf][nf][0] + bz0;
            xrb[(size_t)(o0+1)*HWSZ + p0    ] = c[mf][nf][1] + bz1;
            xrb[(size_t)o0    *HWSZ + p0 + 8] = c[mf][nf][2] + bz0;
            xrb[(size_t)(o0+1)*HWSZ + p0 + 8] = c[mf][nf][3] + bz1;
        }
    }
}

// ---------------- n1: conv1x1 64->32 (FFMA2) ---------------------------------
__global__ void k_n1(const float* __restrict__ b_n1){
    __shared__ __align__(16) float sW[64*32];
    for (int j=threadIdx.x;j<2048;j+=blockDim.x) sW[j]=g_wn1T[j];
    __syncthreads();
    int p = blockIdx.x*blockDim.x + threadIdx.x;
    if (p>=NPIX) return;
    int b=p/HWSZ, hw=p%HWSZ;
    u64 acc[16];
    #pragma unroll
    for (int j=0;j<16;j++) acc[j]=pk2(b_n1[2*j], b_n1[2*j+1]);
    const float* xb = g_xa + (size_t)b*64*HWSZ + hw;
    for (int c=0;c<64;c++){
        u64 vp = bcast2(xb[(size_t)c*HWSZ]);
        const ulonglong2* wp=(const ulonglong2*)&sW[c*32];
        #pragma unroll
        for (int j=0;j<8;j++){
            ulonglong2 ww=wp[j];
            ffma2(acc[2*j],   vp, ww.x);
            ffma2(acc[2*j+1], vp, ww.y);
        }
    }
    float* ob = g_n1 + (size_t)b*32*HWSZ + hw;
    #pragma unroll
    for (int j=0;j<16;j++){
        float2 f=upk(acc[j]);
        ob[(size_t)(2*j  )*HWSZ]=f.x;
        ob[(size_t)(2*j+1)*HWSZ]=f.y;
    }
}

// ---------------- n2: depthwise 3x3 (32 ch) ----------------------------------
__global__ void k_n2(const float* __restrict__ w_n2, const float* __restrict__ b_n2){
    __shared__ float sW[32*9];
    for (int j=threadIdx.x;j<288;j+=blockDim.x) sW[j]=w_n2[j];
    __syncthreads();
    int p = blockIdx.x*blockDim.x + threadIdx.x;
    if (p>=NPIX) return;
    int b=p/HWSZ, hw=p%HWSZ, h=hw/WWD, w=hw%WWD;
    int toff[9]; bool tv[9];
    #pragma unroll
    for (int k=0;k<9;k++){
        int hy=h+k/3-1, wx=w+k%3-1;
        tv[k]=(hy>=0&&hy<HH&&wx>=0&&wx<WWD);
        toff[k]=tv[k]?hy*WWD+wx:0;
    }
    const float* xb = g_n1 + (size_t)b*32*HWSZ;
    float* ob = g_n2 + (size_t)b*32*HWSZ;
    for (int c=0;c<32;c++){
        const float* xc = xb + (size_t)c*HWSZ;
        float acc = b_n2[c];
        #pragma unroll
        for (int k=0;k<9;k++) if (tv[k]) acc += xc[toff[k]]*sW[c*9+k];
        ob[(size_t)c*HWSZ+hw]=acc;
    }
}

// ---------------- final: conv1x1 32->64 + x + xr -> out ----------------------
__global__ void k_final(const float* __restrict__ x, const float* __restrict__ b_n3,
                        float* __restrict__ out){
    __shared__ __align__(16) float sW[32*64];
    for (int j=threadIdx.x;j<2048;j+=blockDim.x) sW[j]=g_wn3T[j];
    __syncthreads();
    int p = blockIdx.x*blockDim.x + threadIdx.x;
    if (p>=NPIX) return;
    int b=p/HWSZ, hw=p%HWSZ;
    u64 acc[32];
    #pragma unroll
    for (int j=0;j<32;j++) acc[j]=pk2(b_n3[2*j], b_n3[2*j+1]);
    const float* xb = g_n2 + (size_t)b*32*HWSZ + hw;
    for (int c=0;c<32;c++){
        u64 vp = bcast2(xb[(size_t)c*HWSZ]);
        const ulonglong2* wp=(const ulonglong2*)&sW[c*64];
        #pragma unroll
        for (int j=0;j<16;j++){
            ulonglong2 ww=wp[j];
            ffma2(acc[2*j],   vp, ww.x);
            ffma2(acc[2*j+1], vp, ww.y);
        }
    }
    const float* xin = x + (size_t)b*64*HWSZ + hw;
    const float* xr  = g_xr + (size_t)b*64*HWSZ + hw;
    float* ob = out + (size_t)b*64*HWSZ + hw;
    #pragma unroll
    for (int j=0;j<32;j++){
        float2 f=upk(acc[j]);
        ob[(size_t)(2*j  )*HWSZ] = xin[(size_t)(2*j  )*HWSZ] + xr[(size_t)(2*j  )*HWSZ] + f.x;
        ob[(size_t)(2*j+1)*HWSZ] = xin[(size_t)(2*j+1)*HWSZ] + xr[(size_t)(2*j+1)*HWSZ] + f.y;
    }
}

// ---------------- launch ------------------------------------------------------
extern "C" void kernel_launch(void* const* d_in, const int* in_sizes, int n_in,
                              void* d_out, int out_size){
    const float* x     = (const float*)d_in[0];
    const float* w_off = (const float*)d_in[1];
    const float* b_off = (const float*)d_in[2];
    const float* w_dc  = (const float*)d_in[3];
    const float* b_dc  = (const float*)d_in[4];
    const float* w_ca1 = (const float*)d_in[5];
    const float* b_ca1 = (const float*)d_in[6];
    const float* w_ca2 = (const float*)d_in[7];
    const float* b_ca2 = (const float*)d_in[8];
    const float* w_sa  = (const float*)d_in[9];
    const float* b_sa  = (const float*)d_in[10];
    const float* w_r1  = (const float*)d_in[11];
    const float* b_r1  = (const float*)d_in[12];
    const float* w_r2  = (const float*)d_in[13];
    const float* b_r2  = (const float*)d_in[14];
    const float* w_n1  = (const float*)d_in[15];
    const float* b_n1  = (const float*)d_in[16];
    const float* w_n2  = (const float*)d_in[17];
    const float* b_n2  = (const float*)d_in[18];
    const float* w_n3  = (const float*)d_in[19];
    const float* b_n3  = (const float*)d_in[20];
    float* out = (float*)d_out;

    const int TPB = 256;
    const int GP  = (NPIX + TPB - 1)/TPB;   // 576
    const int GR  = BB*HH;                  // 768 row-blocks

    k_prep<<<64, 256>>>(w_off, w_dc, w_r1, w_r2, w_n1, w_n3);
    k_cvtx<<<GP, TPB>>>(x);
    k_off_mma<<<GR, 128>>>(b_off);
    // batch-chunked: per-batch g_ds slice (85MB) stays L2-resident for the GEMM
    for (int b = 0; b < BB; b++){
        k_dsample<<<dim3(HH, 9), 192>>>(x, b);
        k_dc_gemm<<<HH, TPB>>>(b_dc, b);
    }
    k_ca_red<<<BB*CCH, 256>>>();
    k_ca_mlp<<<1, 256>>>(w_ca1, b_ca1, w_ca2, b_ca2);
    k_sa_xa<<<GP, TPB>>>(w_sa, b_sa);
    // 2-batch chunks: r1 output slice (75MB) stays L2-resident for r2's 3x re-reads
    for (int h = 0; h < 2; h++){
        k_r1_mma<<<dim3(2*HH,4), TPB>>>(b_r1, 2*h);
        k_r2_mma<<<2*HH, TPB>>>(b_r2, 2*h);
    }
    k_n1<<<GP, TPB>>>(b_n1);
    k_n2<<<GP, TPB>>>(w_n2, b_n2);
    k_final<<<GP, TPB>>>(x, b_n3, out);
}

// round 13
// speedup vs baseline: 1.1592x; 1.1592x over previous
#include <cuda_runtime.h>
#include <math.h>

#define BB 4
#define CCH 64
#define HH 192
#define WWD 192
#define HWSZ (HH*WWD)          // 36864
#define NPIX (BB*HWSZ)         // 147456

typedef unsigned long long u64;
typedef unsigned int u32;

// ---------------- packed helpers --------------------------------------------
__device__ __forceinline__ u64 pk2(float a, float b){
    u64 r; asm("mov.b64 %0, {%1, %2};" : "=l"(r) : "f"(a), "f"(b)); return r;
}
__device__ __forceinline__ u64 bcast2(float a){
    u64 r; asm("mov.b64 %0, {%1, %1};" : "=l"(r) : "f"(a)); return r;
}
__device__ __forceinline__ float2 upk(u64 v){
    float2 f; asm("mov.b64 {%0, %1}, %2;" : "=f"(f.x), "=f"(f.y) : "l"(v)); return f;
}
__device__ __forceinline__ void ffma2(u64 &d, u64 a, u64 b){
    asm("fma.rn.f32x2 %0, %1, %2, %0;" : "+l"(d) : "l"(a), "l"(b));
}
__device__ __forceinline__ u32 f2tf32(float v){
    u32 r; asm("cvt.rna.tf32.f32 %0, %1;" : "=r"(r) : "f"(v)); return r;
}
#define MMA_TF32(C, A0,A1,A2,A3, B0,B1) \
    asm volatile("mma.sync.aligned.m16n8k8.row.col.f32.tf32.tf32.f32 " \
        "{%0,%1,%2,%3}, {%4,%5,%6,%7}, {%8,%9}, {%0,%1,%2,%3};" \
        : "+f"(C[0]), "+f"(C[1]), "+f"(C[2]), "+f"(C[3]) \
        : "r"(A0), "r"(A1), "r"(A2), "r"(A3), "r"(B0), "r"(B1))

// ---------------- scratch (device globals) ----------------------------------
__device__ float g_off  [BB*18*HWSZ];
__device__ float g_mask [BB*9 *HWSZ];
__device__ float g_xd   [BB*CCH*HWSZ];
__device__ float g_sau  [BB*9*HWSZ];     // spatial-attn partial planes u_k
__device__ u32   g_xatf [BB*CCH*HWSZ];   // tf32 bits of xa (also read as float)
__device__ u32   g_xtf  [BB*CCH*HWSZ];   // tf32 bits of x
__device__ u32   g_ds   [(size_t)BB*576*HWSZ];  // sampled deform planes, tf32 bits
__device__ float g_r1   [BB*256*HWSZ];   // tf32-rounded bit patterns (as float)
__device__ float g_xr   [BB*CCH*HWSZ];
__device__ float g_n1   [BB*32*HWSZ];
__device__ float g_n2   [BB*32*HWSZ];
__device__ float g_camean[BB*CCH];
__device__ float g_ca   [BB*CCH];

// tf32 weights in per-chunk staging order
__device__ u32   g_wofftf[8*2304];    // [cc(8)][tap(9)][kc(8)][o(32 pad)]
__device__ u32   g_wdctf2[576*64];    // [k=tap*64+c][o]
__device__ u32   g_wr1tf [4*4096];    // [ocq(4)][cc(8)][kc(8)][o(64)]
__device__ u32   g_wr2Tf [32*4608];   // [cc(32)][tap(9)][kc(8)][o(64)]
__device__ float g_wn1T  [64*32];     // [c][o]
__device__ float g_wn3T  [32*64];     // [c][o]

__device__ __forceinline__ float leakyf(float v){ return v >= 0.f ? v : 0.1f*v; }
__device__ __forceinline__ float sigmf(float v){ return 1.f/(1.f+__expf(-v)); }

// ---------------- weight prep -----------------------------------------------
__global__ void k_prep(const float* __restrict__ w_off, const float* __restrict__ w_dc,
                       const float* __restrict__ w_r1,  const float* __restrict__ w_r2,
                       const float* __restrict__ w_n1,  const float* __restrict__ w_n3){
    int t = blockIdx.x*blockDim.x + threadIdx.x;
    int nt = gridDim.x*blockDim.x;
    for (int i=t;i<8*2304;i+=nt){
        int cc=i/2304, rem=i%2304, tap=rem>>8, kc=(rem>>5)&7, o=rem&31;
        g_wofftf[i] = (o<27) ? f2tf32(w_off[(o*64 + cc*8+kc)*9 + tap]) : 0u;
    }
    for (int i=t;i<576*64;i+=nt){
        int k=i>>6, o=i&63, c=k&63, tap=k>>6;
        g_wdctf2[i] = f2tf32(w_dc[(o*64+c)*9+tap]);
    }
    for (int i=t;i<4*4096;i+=nt){
        int q=i>>12, rem=i&4095, cc=rem>>9, kc=(rem>>6)&7, o=rem&63;
        g_wr1tf[i] = f2tf32(w_r1[(q*64+o)*64 + cc*8+kc]);
    }
    for (int i=t;i<32*4608;i+=nt){
        int cc=i/4608, rem=i%4608, tap=rem>>9, kc=(rem>>6)&7, o=rem&63;
        g_wr2Tf[i] = f2tf32(w_r2[(o*256 + cc*8 + kc)*9 + tap]);
    }
    for (int i=t;i<64*32;i+=nt){ int o=i%32; int c=i/32; g_wn1T[i]=w_n1[o*64+c]; }
    for (int i=t;i<32*64;i+=nt){ int o=i%64; int c=i/64; g_wn3T[i]=w_n3[o*32+c]; }
}

// ---------------- x -> tf32 bits copy ----------------------------------------
__global__ void k_cvtx(const float* __restrict__ x){
    int nt = gridDim.x*blockDim.x;
    const float4* src = (const float4*)x;
    uint4* dst = (uint4*)g_xtf;
    const int NV = BB*CCH*HWSZ/4;          // 2,359,296 uint4
    for (int i = blockIdx.x*blockDim.x + threadIdx.x; i < NV; i += nt){
        float4 v = src[i];
        dst[i] = make_uint4(f2tf32(v.x), f2tf32(v.y), f2tf32(v.z), f2tf32(v.w));
    }
}

// ---------------- offset conv 3x3 64->27 via MMA -----------------------------
#define ASX 200
#define BSO 40
__global__ __launch_bounds__(128,4) void k_off_mma(const float* __restrict__ b_off){
    __shared__ __align__(16) u32 As[3*8*ASX];   // [ri][kc][200]
    __shared__ __align__(16) u32 Bs[9*8*BSO];   // [tap][kc][40]
    int blk = blockIdx.x;
    int b = blk / HH, r = blk % HH;
    int tid = threadIdx.x;
    int wm = tid >> 5, lane = tid & 31;
    int lg = lane >> 2, lt = lane & 3;

    float c[3][4][4];
    #pragma unroll
    for (int mf=0;mf<3;mf++)
        #pragma unroll
        for (int nf=0;nf<4;nf++)
            #pragma unroll
            for (int q=0;q<4;q++) c[mf][nf][q]=0.f;

    for (int cc=0; cc<8; cc++){
        if (tid < 48){ int rc = tid>>1, side = tid&1;
            As[rc*ASX + 3 + side*193] = 0u; }
        #pragma unroll
        for (int j=0;j<9;j++){
            int i = tid + 128*j;                  // < 1152
            int rc = i/48, q = i - rc*48;
            int ri = rc>>3, kc = rc&7;
            int gr = r - 1 + ri;
            uint4 v = make_uint4(0u,0u,0u,0u);
            if (gr>=0 && gr<HH)
                v = *(const uint4*)(&g_xtf[((size_t)(b*64 + cc*8 + kc))*HWSZ + gr*WWD + 4*q]);
            *(uint4*)&As[rc*ASX + 4 + 4*q] = v;
        }
        #pragma unroll
        for (int j=0;j<5;j++){
            int i = tid + 128*j;
            if (i < 576){
                int wd = 4*i;
                int tap = wd>>8, rem = wd&255, kc = rem>>5, o = rem&31;
                *(uint4*)&Bs[(tap*8+kc)*BSO + o] = *(const uint4*)&g_wofftf[cc*2304 + wd];
            }
        }
        __syncthreads();
        #pragma unroll
        for (int tap=0; tap<9; tap++){
            int dh = tap/3, dw = tap%3;
            u32 a[3][4];
            #pragma unroll
            for (int mf=0;mf<3;mf++){
                int p0 = wm*48 + mf*16 + lg;
                int col0 = p0 + dw + 3;
                const u32* alo = &As[(dh*8+lt  )*ASX];
                const u32* ahi = &As[(dh*8+lt+4)*ASX];
                a[mf][0]=alo[col0]; a[mf][1]=alo[col0+8];
                a[mf][2]=ahi[col0]; a[mf][3]=ahi[col0+8];
            }
            u32 bb[4][2];
            #pragma unroll
            for (int nf=0;nf<4;nf++){
                int n = nf*8 + lg;
                bb[nf][0] = Bs[(tap*8+lt  )*BSO + n];
                bb[nf][1] = Bs[(tap*8+lt+4)*BSO + n];
            }
            #pragma unroll
            for (int mf=0;mf<3;mf++)
                #pragma unroll
                for (int nf=0;nf<4;nf++)
                    MMA_TF32(c[mf][nf], a[mf][0],a[mf][1],a[mf][2],a[mf][3], bb[nf][0],bb[nf][1]);
        }
        __syncthreads();
    }
    int rbase = r*WWD;
    #pragma unroll
    for (int mf=0;mf<3;mf++){
        int p0 = wm*48 + mf*16 + lg;
        #pragma unroll
        for (int nf=0;nf<4;nf++){
            int o0 = nf*8 + 2*lt;
            #pragma unroll
            for (int q=0;q<4;q++){
                int o = o0 + (q&1);
                int p = p0 + (q>>1)*8;
                if (o < 27){
                    float v = leakyf(c[mf][nf][q] + b_off[o]);
                    if (o < 18) g_off [(b*18+o)*HWSZ + rbase + p] = v;
                    else        g_mask[(b*9+(o-18))*HWSZ + rbase + p] = sigmf(v);
                }
            }
        }
    }
}

// ---------------- deform sampler (monolithic, R11 config) --------------------
__global__ __launch_bounds__(192,8) void k_dsample(const float* __restrict__ x){
    int b = blockIdx.x / HH, r = blockIdx.x % HH;
    int tap = blockIdx.y;
    int px = threadIdx.x;
    int hw = r*WWD + px;

    float dy = g_off[(b*18+2*tap  )*HWSZ+hw];
    float dx = g_off[(b*18+2*tap+1)*HWSZ+hw];
    float m  = g_mask[(b*9+tap)*HWSZ+hw];
    float py = (float)r  + (float)(tap/3-1) + dy;
    float pxf= (float)px + (float)(tap%3-1) + dx;
    float y0f = floorf(py), x0f = floorf(pxf);
    float wy = py - y0f,  wx = pxf - x0f;
    int y0=(int)y0f, x0=(int)x0f, y1=y0+1, x1=x0+1;
    bool vy0=(y0>=0&&y0<HH), vy1=(y1>=0&&y1<HH);
    bool vx0=(x0>=0&&x0<WWD), vx1=(x1>=0&&x1<WWD);
    float w00=(1.f-wy)*(1.f-wx)*((vy0&&vx0)?m:0.f);
    float w01=(1.f-wy)*wx      *((vy0&&vx1)?m:0.f);
    float w10=wy*(1.f-wx)      *((vy1&&vx0)?m:0.f);
    float w11=wy*wx            *((vy1&&vx1)?m:0.f);
    int cy0=min(max(y0,0),HH-1), cy1=min(max(y1,0),HH-1);
    int cx0=min(max(x0,0),WWD-1), cx1=min(max(x1,0),WWD-1);
    int i00=cy0*WWD+cx0, i01=cy0*WWD+cx1, i10=cy1*WWD+cx0, i11=cy1*WWD+cx1;

    const float* xb = x + (size_t)b*64*HWSZ;
    u32* dst = g_ds + (size_t)(b*576 + tap*64)*HWSZ + hw;
    #pragma unroll 8
    for (int c=0;c<64;c++){
        const float* xc = xb + (size_t)c*HWSZ;
        float v = w00*xc[i00] + w01*xc[i01] + w10*xc[i10] + w11*xc[i11];
        dst[(size_t)c*HWSZ] = f2tf32(v);
    }
}

// ---------------- dc GEMM: 576 -> 64 over sampled planes ---------------------
__global__ __launch_bounds__(256,2) void k_dc_gemm(const float* __restrict__ b_dc){
    __shared__ __align__(16) u32 As[16*ASX];    // 12.8KB
    __shared__ __align__(16) u32 Bs[16*72];     // 4.6KB
    int b = blockIdx.x / HH, r = blockIdx.x % HH;
    int tid = threadIdx.x;
    int w  = tid >> 5, lane = tid & 31;
    int wm = w & 3, wn = w >> 2;
    int lg = lane >> 2, lt = lane & 3;

    float c[3][4][4];
    #pragma unroll
    for (int mf=0;mf<3;mf++)
        #pragma unroll
        for (int nf=0;nf<4;nf++)
            #pragma unroll
            for (int q=0;q<4;q++) c[mf][nf][q]=0.f;

    const u32* dsb = g_ds + (size_t)b*576*HWSZ + r*WWD;

    for (int ch=0; ch<36; ch++){
        #pragma unroll
        for (int j=0;j<3;j++){
            int i = tid + 256*j;                  // < 768
            int kc = i/48, q = i - kc*48;
            *(uint4*)&As[kc*ASX + 4*q] =
                *(const uint4*)&dsb[(size_t)(ch*16 + kc)*HWSZ + 4*q];
        }
        {
            int wd = 4*tid;                       // < 1024
            int kc = wd>>6, o = wd&63;
            *(uint4*)&Bs[kc*72 + o] = *(const uint4*)&g_wdctf2[ch*1024 + wd];
        }
        __syncthreads();
        #pragma unroll
        for (int ks=0; ks<2; ks++){
            u32 a[3][4];
            #pragma unroll
            for (int mf=0;mf<3;mf++){
                int p0 = wm*48 + mf*16 + lg;
                const u32* alo = &As[(ks*8+lt  )*ASX];
                const u32* ahi = &As[(ks*8+lt+4)*ASX];
                a[mf][0]=alo[p0]; a[mf][1]=alo[p0+8];
                a[mf][2]=ahi[p0]; a[mf][3]=ahi[p0+8];
            }
            u32 bb[4][2];
            #pragma unroll
            for (int nf=0;nf<4;nf++){
                int n = wn*32 + nf*8 + lg;
                bb[nf][0] = Bs[(ks*8+lt  )*72 + n];
                bb[nf][1] = Bs[(ks*8+lt+4)*72 + n];
            }
            #pragma unroll
            for (int mf=0;mf<3;mf++)
                #pragma unroll
                for (int nf=0;nf<4;nf++)
                    MMA_TF32(c[mf][nf], a[mf][0],a[mf][1],a[mf][2],a[mf][3], bb[nf][0],bb[nf][1]);
        }
        __syncthreads();
    }
    float* xdb = g_xd + (size_t)b*64*HWSZ + r*WWD;
    #pragma unroll
    for (int mf=0;mf<3;mf++){
        int p0 = wm*48 + mf*16 + lg;
        #pragma unroll
        for (int nf=0;nf<4;nf++){
            int o0 = wn*32 + nf*8 + 2*lt;
            float bz0 = b_dc[o0], bz1 = b_dc[o0+1];
            xdb[(size_t)o0    *HWSZ + p0    ] = c[mf][nf][0] + bz0;
            xdb[(size_t)(o0+1)*HWSZ + p0    ] = c[mf][nf][1] + bz1;
            xdb[(size_t)o0    *HWSZ + p0 + 8] = c[mf][nf][2] + bz0;
            xdb[(size_t)(o0+1)*HWSZ + p0 + 8] = c[mf][nf][3] + bz1;
        }
    }
}

// ---------------- channel-attention mean reduce ------------------------------
__global__ void k_ca_red(){
    int bc = blockIdx.x;
    const float4* src = (const float4*)(g_xd + (size_t)bc*HWSZ);
    float s = 0.f;
    for (int i=threadIdx.x;i<HWSZ/4;i+=blockDim.x){
        float4 v = src[i]; s += (v.x+v.y)+(v.z+v.w);
    }
    __shared__ float red[256];
    red[threadIdx.x]=s; __syncthreads();
    for (int st=128;st>0;st>>=1){ if (threadIdx.x<st) red[threadIdx.x]+=red[threadIdx.x+st]; __syncthreads(); }
    if (threadIdx.x==0) g_camean[bc] = red[0]*(1.f/(float)HWSZ);
}

// ---------------- channel-attention MLP --------------------------------------
__global__ void k_ca_mlp(const float* __restrict__ w_ca1, const float* __restrict__ b_ca1,
                         const float* __restrict__ w_ca2, const float* __restrict__ b_ca2){
    __shared__ float hid[4*8];
    int t = threadIdx.x;
    if (t<32){ int b=t/8, j=t%8;
        float s = b_ca1[j];
        for (int c=0;c<64;c++) s += w_ca1[j*64+c]*g_camean[b*64+c];
        hid[b*8+j] = fmaxf(s,0.f);
    }
    __syncthreads();
    if (t<256){ int b=t/64, o=t%64;
        float s = b_ca2[o];
        #pragma unroll
        for (int j=0;j<8;j++) s += w_ca2[o*8+j]*hid[b*8+j];
        g_ca[t] = sigmf(s);
    }
}

// ---------------- sa pass 1: u_k[p] = sum_c W[c,k]*xd[c,p]  ------------------
__global__ void k_sa1(const float* __restrict__ w_sa){
    __shared__ float sW[64*9];
    for (int j=threadIdx.x;j<576;j+=blockDim.x) sW[j]=w_sa[j];
    __syncthreads();
    int p = blockIdx.x*blockDim.x + threadIdx.x;
    if (p>=NPIX) return;
    int b=p/HWSZ, hw=p%HWSZ;
    float u[9];
    #pragma unroll
    for (int k=0;k<9;k++) u[k]=0.f;
    const float* xb = g_xd + (size_t)b*64*HWSZ + hw;
    for (int c=0;c<64;c++){
        float v = xb[(size_t)c*HWSZ];
        #pragma unroll
        for (int k=0;k<9;k++) u[k] += v*sW[c*9+k];
    }
    #pragma unroll
    for (int k=0;k<9;k++) g_sau[(b*9+k)*HWSZ+hw] = u[k];
}

// ---------------- sa pass 2: shift-add 9 planes, sigmoid, xa=xd*(ca+sa) ------
__global__ void k_sa_xa2(const float* __restrict__ b_sa){
    int p = blockIdx.x*blockDim.x + threadIdx.x;
    if (p>=NPIX) return;
    int b=p/HWSZ, hw=p%HWSZ, h=hw/WWD, w=hw%WWD;
    float s = b_sa[0];
    #pragma unroll
    for (int k=0;k<9;k++){
        int hy=h+k/3-1, wx=w+k%3-1;
        if (hy>=0 && hy<HH && wx>=0 && wx<WWD)
            s += g_sau[(b*9+k)*HWSZ + hy*WWD+wx];
    }
    s = sigmf(s);
    const float* xb = g_xd + (size_t)b*64*HWSZ + hw;
    u32* ob = g_xatf + (size_t)b*64*HWSZ + hw;
    for (int c=0;c<64;c++){
        float scale = g_ca[b*64+c] + s;
        ob[(size_t)c*HWSZ] = f2tf32(xb[(size_t)c*HWSZ]*scale);
    }
}

// ---------------- r1: conv1x1 64->256 via MMA, leaky, store tf32 -------------
__global__ __launch_bounds__(256,2) void k_r1_mma(const float* __restrict__ b_r1){
    __shared__ __align__(16) u32 As[8*ASX];     // 6.4KB
    __shared__ __align__(16) u32 Bs[8*72];      // 2.3KB
    int blk = blockIdx.x;
    int b = blk / HH, r = blk % HH;
    int oc0 = blockIdx.y*64;
    int tid = threadIdx.x;
    int w  = tid >> 5, lane = tid & 31;
    int wm = w & 3, wn = w >> 2;
    int lg = lane >> 2, lt = lane & 3;

    float c[3][4][4];
    #pragma unroll
    for (int mf=0;mf<3;mf++)
        #pragma unroll
        for (int nf=0;nf<4;nf++)
            #pragma unroll
            for (int q=0;q<4;q++) c[mf][nf][q]=0.f;

    for (int cc=0; cc<8; cc++){
        #pragma unroll
        for (int j=0;j<2;j++){
            int i = tid + 256*j;
            if (i < 384){
                int kc = i/48, q = i - kc*48;
                *(uint4*)&As[kc*ASX + 4*q] =
                    *(const uint4*)&g_xatf[((size_t)(b*64 + cc*8 + kc))*HWSZ + r*WWD + 4*q];
            }
        }
        if (tid < 128){
            int wd = 4*tid;
            int kc = wd>>6, o = wd&63;
            *(uint4*)&Bs[kc*72 + o] = *(const uint4*)&g_wr1tf[blockIdx.y*4096 + cc*512 + wd];
        }
        __syncthreads();
        u32 a[3][4];
        #pragma unroll
        for (int mf=0;mf<3;mf++){
            int p0 = wm*48 + mf*16 + lg;
            const u32* alo = &As[lt*ASX];
            const u32* ahi = &As[(lt+4)*ASX];
            a[mf][0]=alo[p0]; a[mf][1]=alo[p0+8];
            a[mf][2]=ahi[p0]; a[mf][3]=ahi[p0+8];
        }
        u32 bb[4][2];
        #pragma unroll
        for (int nf=0;nf<4;nf++){
            int n = wn*32 + nf*8 + lg;
            bb[nf][0] = Bs[lt*72 + n];
            bb[nf][1] = Bs[(lt+4)*72 + n];
        }
        #pragma unroll
        for (int mf=0;mf<3;mf++)
            #pragma unroll
            for (int nf=0;nf<4;nf++)
                MMA_TF32(c[mf][nf], a[mf][0],a[mf][1],a[mf][2],a[mf][3], bb[nf][0],bb[nf][1]);
        __syncthreads();
    }
    float* ob = g_r1 + ((size_t)b*256+oc0)*HWSZ + r*WWD;
    #pragma unroll
    for (int mf=0;mf<3;mf++){
        int p0 = wm*48 + mf*16 + lg;
        #pragma unroll
        for (int nf=0;nf<4;nf++){
            int o0 = wn*32 + nf*8 + 2*lt;
            float bz0 = b_r1[oc0+o0], bz1 = b_r1[oc0+o0+1];
            ob[(size_t)o0    *HWSZ + p0    ] = __uint_as_float(f2tf32(leakyf(c[mf][nf][0] + bz0)));
            ob[(size_t)(o0+1)*HWSZ + p0    ] = __uint_as_float(f2tf32(leakyf(c[mf][nf][1] + bz1)));
            ob[(size_t)o0    *HWSZ + p0 + 8] = __uint_as_float(f2tf32(leakyf(c[mf][nf][2] + bz0)));
            ob[(size_t)(o0+1)*HWSZ + p0 + 8] = __uint_as_float(f2tf32(leakyf(c[mf][nf][3] + bz1)));
        }
    }
}

// ---------------- r2: conv3x3 256->64 via MMA --------------------------------
#define AS2 200
#define BS2 72
__global__ __launch_bounds__(256,2) void k_r2_mma(const float* __restrict__ b_r2){
    __shared__ __align__(16) u32 As[3*8*AS2];
    __shared__ __align__(16) u32 Bs[9*8*BS2];
    int blk = blockIdx.x;
    int b = blk / HH, r = blk % HH;
    int tid = threadIdx.x;
    int w  = tid >> 5, lane = tid & 31;
    int wm = w & 3, wn = w >> 2;
    int lg = lane >> 2, lt = lane & 3;

    float c[3][4][4];
    #pragma unroll
    for (int mf=0;mf<3;mf++)
        #pragma unroll
        for (int nf=0;nf<4;nf++)
            #pragma unroll
            for (int q=0;q<4;q++) c[mf][nf][q]=0.f;

    for (int cc=0; cc<32; cc++){
        if (tid < 48){ int rc = tid>>1, side = tid&1;
            As[rc*AS2 + 3 + side*193] = 0u; }
        #pragma unroll
        for (int j=0;j<5;j++){
            int i = tid + 256*j;
            if (i < 1152){
                int rc = i/48, q = i - rc*48;
                int ri = rc>>3, kc = rc&7;
                int gr = r - 1 + ri;
                uint4 v = make_uint4(0u,0u,0u,0u);
                if (gr>=0 && gr<HH)
                    v = *(const uint4*)(&g_r1[((size_t)(b*256 + cc*8 + kc))*HWSZ + gr*WWD + 4*q]);
                *(uint4*)&As[rc*AS2 + 4 + 4*q] = v;
            }
        }
        #pragma unroll
        for (int j=0;j<5;j++){
            int i = tid + 256*j;
            if (i < 1152){
                int wd = 4*i;
                int tap = wd>>9, rem = wd&511, kc = rem>>6, o = rem&63;
                *(uint4*)&Bs[(tap*8+kc)*BS2 + o] = *(const uint4*)&g_wr2Tf[cc*4608 + wd];
            }
        }
        __syncthreads();
        #pragma unroll
        for (int tap=0; tap<9; tap++){
            int dh = tap/3, dw = tap%3;
            u32 a[3][4];
            #pragma unroll
            for (int mf=0;mf<3;mf++){
                int p0 = wm*48 + mf*16 + lg;
                int col0 = p0 + dw + 3;
                const u32* alo = &As[(dh*8+lt  )*AS2];
                const u32* ahi = &As[(dh*8+lt+4)*AS2];
                a[mf][0]=alo[col0]; a[mf][1]=alo[col0+8];
                a[mf][2]=ahi[col0]; a[mf][3]=ahi[col0+8];
            }
            u32 bb[4][2];
            #pragma unroll
            for (int nf=0;nf<4;nf++){
                int n = wn*32 + nf*8 + lg;
                bb[nf][0] = Bs[(tap*8+lt  )*BS2 + n];
                bb[nf][1] = Bs[(tap*8+lt+4)*BS2 + n];
            }
            #pragma unroll
            for (int mf=0;mf<3;mf++)
                #pragma unroll
                for (int nf=0;nf<4;nf++)
                    MMA_TF32(c[mf][nf], a[mf][0],a[mf][1],a[mf][2],a[mf][3], bb[nf][0],bb[nf][1]);
        }
        __syncthreads();
    }
    float* xrb = g_xr + (size_t)b*64*HWSZ + r*WWD;
    #pragma unroll
    for (int mf=0;mf<3;mf++){
        int p0 = wm*48 + mf*16 + lg;
        #pragma unroll
        for (int nf=0;nf<4;nf++){
            int o0 = wn*32 + nf*8 + 2*lt;
            float bz0 = b_r2[o0], bz1 = b_r2[o0+1];
            xrb[(size_t)o0    *HWSZ + p0    ] = c[mf][nf][0] + bz0;
            xrb[(size_t)(o0+1)*HWSZ + p0    ] = c[mf][nf][1] + bz1;
            xrb[(size_t)o0    *HWSZ + p0 + 8] = c[mf][nf][2] + bz0;
            xrb[(size_t)(o0+1)*HWSZ + p0 + 8] = c[mf][nf][3] + bz1;
        }
    }
}

// ---------------- n1: conv1x1 64->32 (FFMA2, reads tf32-as-float xa) ---------
__global__ void k_n1(const float* __restrict__ b_n1){
    __shared__ __align__(16) float sW[64*32];
    for (int j=threadIdx.x;j<2048;j+=blockDim.x) sW[j]=g_wn1T[j];
    __syncthreads();
    int p = blockIdx.x*blockDim.x + threadIdx.x;
    if (p>=NPIX) return;
    int b=p/HWSZ, hw=p%HWSZ;
    u64 acc[16];
    #pragma unroll
    for (int j=0;j<16;j++) acc[j]=pk2(b_n1[2*j], b_n1[2*j+1]);
    const float* xb = (const float*)g_xatf + (size_t)b*64*HWSZ + hw;
    for (int c=0;c<64;c++){
        u64 vp = bcast2(xb[(size_t)c*HWSZ]);
        const ulonglong2* wp=(const ulonglong2*)&sW[c*32];
        #pragma unroll
        for (int j=0;j<8;j++){
            ulonglong2 ww=wp[j];
            ffma2(acc[2*j],   vp, ww.x);
            ffma2(acc[2*j+1], vp, ww.y);
        }
    }
    float* ob = g_n1 + (size_t)b*32*HWSZ + hw;
    #pragma unroll
    for (int j=0;j<16;j++){
        float2 f=upk(acc[j]);
        ob[(size_t)(2*j  )*HWSZ]=f.x;
        ob[(size_t)(2*j+1)*HWSZ]=f.y;
    }
}

// ---------------- n2: depthwise 3x3 (32 ch) ----------------------------------
__global__ void k_n2(const float* __restrict__ w_n2, const float* __restrict__ b_n2){
    __shared__ float sW[32*9];
    for (int j=threadIdx.x;j<288;j+=blockDim.x) sW[j]=w_n2[j];
    __syncthreads();
    int p = blockIdx.x*blockDim.x + threadIdx.x;
    if (p>=NPIX) return;
    int b=p/HWSZ, hw=p%HWSZ, h=hw/WWD, w=hw%WWD;
    int toff[9]; bool tv[9];
    #pragma unroll
    for (int k=0;k<9;k++){
        int hy=h+k/3-1, wx=w+k%3-1;
        tv[k]=(hy>=0&&hy<HH&&wx>=0&&wx<WWD);
        toff[k]=tv[k]?hy*WWD+wx:0;
    }
    const float* xb = g_n1 + (size_t)b*32*HWSZ;
    float* ob = g_n2 + (size_t)b*32*HWSZ;
    for (int c=0;c<32;c++){
        const float* xc = xb + (size_t)c*HWSZ;
        float acc = b_n2[c];
        #pragma unroll
        for (int k=0;k<9;k++) if (tv[k]) acc += xc[toff[k]]*sW[c*9+k];
        ob[(size_t)c*HWSZ+hw]=acc;
    }
}

// ---------------- final: conv1x1 32->64 + x + xr -> out ----------------------
__global__ void k_final(const float* __restrict__ x, const float* __restrict__ b_n3,
                        float* __restrict__ out){
    __shared__ __align__(16) float sW[32*64];
    for (int j=threadIdx.x;j<2048;j+=blockDim.x) sW[j]=g_wn3T[j];
    __syncthreads();
    int p = blockIdx.x*blockDim.x + threadIdx.x;
    if (p>=NPIX) return;
    int b=p/HWSZ, hw=p%HWSZ;
    u64 acc[32];
    #pragma unroll
    for (int j=0;j<32;j++) acc[j]=pk2(b_n3[2*j], b_n3[2*j+1]);
    const float* xb = g_n2 + (size_t)b*32*HWSZ + hw;
    for (int c=0;c<32;c++){
        u64 vp = bcast2(xb[(size_t)c*HWSZ]);
        const ulonglong2* wp=(const ulonglong2*)&sW[c*64];
        #pragma unroll
        for (int j=0;j<16;j++){
            ulonglong2 ww=wp[j];
            ffma2(acc[2*j],   vp, ww.x);
            ffma2(acc[2*j+1], vp, ww.y);
        }
    }
    const float* xin = x + (size_t)b*64*HWSZ + hw;
    const float* xr  = g_xr + (size_t)b*64*HWSZ + hw;
    float* ob = out + (size_t)b*64*HWSZ + hw;
    #pragma unroll
    for (int j=0;j<32;j++){
        float2 f=upk(acc[j]);
        ob[(size_t)(2*j  )*HWSZ] = xin[(size_t)(2*j  )*HWSZ] + xr[(size_t)(2*j  )*HWSZ] + f.x;
        ob[(size_t)(2*j+1)*HWSZ] = xin[(size_t)(2*j+1)*HWSZ] + xr[(size_t)(2*j+1)*HWSZ] + f.y;
    }
}

// ---------------- launch ------------------------------------------------------
extern "C" void kernel_launch(void* const* d_in, const int* in_sizes, int n_in,
                              void* d_out, int out_size){
    const float* x     = (const float*)d_in[0];
    const float* w_off = (const float*)d_in[1];
    const float* b_off = (const float*)d_in[2];
    const float* w_dc  = (const float*)d_in[3];
    const float* b_dc  = (const float*)d_in[4];
    const float* w_ca1 = (const float*)d_in[5];
    const float* b_ca1 = (const float*)d_in[6];
    const float* w_ca2 = (const float*)d_in[7];
    const float* b_ca2 = (const float*)d_in[8];
    const float* w_sa  = (const float*)d_in[9];
    const float* b_sa  = (const float*)d_in[10];
    const float* w_r1  = (const float*)d_in[11];
    const float* b_r1  = (const float*)d_in[12];
    const float* w_r2  = (const float*)d_in[13];
    const float* b_r2  = (const float*)d_in[14];
    const float* w_n1  = (const float*)d_in[15];
    const float* b_n1  = (const float*)d_in[16];
    const float* w_n2  = (const float*)d_in[17];
    const float* b_n2  = (const float*)d_in[18];
    const float* w_n3  = (const float*)d_in[19];
    const float* b_n3  = (const float*)d_in[20];
    float* out = (float*)d_out;

    const int TPB = 256;
    const int GP  = (NPIX + TPB - 1)/TPB;   // 576
    const int GR  = BB*HH;                  // 768 row-blocks

    k_prep<<<64, 256>>>(w_off, w_dc, w_r1, w_r2, w_n1, w_n3);
    k_cvtx<<<GP, TPB>>>(x);
    k_off_mma<<<GR, 128>>>(b_off);
    k_dsample<<<dim3(GR, 9), 192>>>(x);
    k_dc_gemm<<<GR, TPB>>>(b_dc);
    k_ca_red<<<BB*CCH, 256>>>();
    k_ca_mlp<<<1, 256>>>(w_ca1, b_ca1, w_ca2, b_ca2);
    k_sa1<<<GP, TPB>>>(w_sa);
    k_sa_xa2<<<GP, TPB>>>(b_sa);
    k_r1_mma<<<dim3(GR,4), TPB>>>(b_r1);
    k_r2_mma<<<GR, TPB>>>(b_r2);
    k_n1<<<GP, TPB>>>(b_n1);
    k_n2<<<GP, TPB>>>(w_n2, b_n2);
    k_final<<<GP, TPB>>>(x, b_n3, out);
}

// round 14
// speedup vs baseline: 1.2366x; 1.0667x over previous
#include <cuda_runtime.h>
#include <math.h>

#define BB 4
#define CCH 64
#define HH 192
#define WWD 192
#define HWSZ (HH*WWD)          // 36864
#define NPIX (BB*HWSZ)         // 147456

typedef unsigned long long u64;
typedef unsigned int u32;

// ---------------- packed helpers --------------------------------------------
__device__ __forceinline__ u64 pk2(float a, float b){
    u64 r; asm("mov.b64 %0, {%1, %2};" : "=l"(r) : "f"(a), "f"(b)); return r;
}
__device__ __forceinline__ u64 bcast2(float a){
    u64 r; asm("mov.b64 %0, {%1, %1};" : "=l"(r) : "f"(a)); return r;
}
__device__ __forceinline__ float2 upk(u64 v){
    float2 f; asm("mov.b64 {%0, %1}, %2;" : "=f"(f.x), "=f"(f.y) : "l"(v)); return f;
}
__device__ __forceinline__ void ffma2(u64 &d, u64 a, u64 b){
    asm("fma.rn.f32x2 %0, %1, %2, %0;" : "+l"(d) : "l"(a), "l"(b));
}
__device__ __forceinline__ u32 f2tf32(float v){
    u32 r; asm("cvt.rna.tf32.f32 %0, %1;" : "=r"(r) : "f"(v)); return r;
}
#define MMA_TF32(C, A0,A1,A2,A3, B0,B1) \
    asm volatile("mma.sync.aligned.m16n8k8.row.col.f32.tf32.tf32.f32 " \
        "{%0,%1,%2,%3}, {%4,%5,%6,%7}, {%8,%9}, {%0,%1,%2,%3};" \
        : "+f"(C[0]), "+f"(C[1]), "+f"(C[2]), "+f"(C[3]) \
        : "r"(A0), "r"(A1), "r"(A2), "r"(A3), "r"(B0), "r"(B1))

// ---------------- cp.async helpers -------------------------------------------
__device__ __forceinline__ void cp16(u32 smem, const void* g, int srcsize){
    asm volatile("cp.async.cg.shared.global [%0], [%1], 16, %2;"
                 :: "r"(smem), "l"(g), "r"(srcsize) : "memory");
}
__device__ __forceinline__ void cp_commit(){
    asm volatile("cp.async.commit_group;" ::: "memory");
}
template<int N> __device__ __forceinline__ void cp_wait(){
    asm volatile("cp.async.wait_group %0;" :: "n"(N) : "memory");
}

// ---------------- scratch (device globals) ----------------------------------
__device__ float g_off  [BB*18*HWSZ];
__device__ float g_mask [BB*9 *HWSZ];
__device__ float g_xd   [BB*CCH*HWSZ];
__device__ float g_sau  [BB*9*HWSZ];     // spatial-attn partial planes u_k
__device__ u32   g_xatf [BB*CCH*HWSZ];   // tf32 bits of xa (also read as float)
__device__ u32   g_xtf  [BB*CCH*HWSZ];   // tf32 bits of x
__device__ u32   g_ds   [(size_t)BB*576*HWSZ];  // sampled deform planes, tf32 bits
__device__ float g_r1   [BB*256*HWSZ];   // tf32-rounded bit patterns (as float)
__device__ float g_xr   [BB*CCH*HWSZ];
__device__ float g_n1   [BB*32*HWSZ];
__device__ float g_n2   [BB*32*HWSZ];
__device__ float g_camean[BB*CCH];
__device__ float g_ca   [BB*CCH];

// tf32 weights in per-chunk staging order
__device__ u32   g_wofftf[8*2304];    // [cc(8)][tap(9)][kc(8)][o(32 pad)]
__device__ u32   g_wdctf2[576*64];    // [k=tap*64+c][o]
__device__ u32   g_wr1tf [4*4096];    // [ocq(4)][cc(8)][kc(8)][o(64)]
__device__ u32   g_wr2Tf [32*4608];   // [cc(32)][tap(9)][kc(8)][o(64)]
__device__ float g_wn1T  [64*32];     // [c][o]
__device__ float g_wn3T  [32*64];     // [c][o]

__device__ __forceinline__ float leakyf(float v){ return v >= 0.f ? v : 0.1f*v; }
__device__ __forceinline__ float sigmf(float v){ return 1.f/(1.f+__expf(-v)); }

// ---------------- weight prep -----------------------------------------------
__global__ void k_prep(const float* __restrict__ w_off, const float* __restrict__ w_dc,
                       const float* __restrict__ w_r1,  const float* __restrict__ w_r2,
                       const float* __restrict__ w_n1,  const float* __restrict__ w_n3){
    int t = blockIdx.x*blockDim.x + threadIdx.x;
    int nt = gridDim.x*blockDim.x;
    for (int i=t;i<8*2304;i+=nt){
        int cc=i/2304, rem=i%2304, tap=rem>>8, kc=(rem>>5)&7, o=rem&31;
        g_wofftf[i] = (o<27) ? f2tf32(w_off[(o*64 + cc*8+kc)*9 + tap]) : 0u;
    }
    for (int i=t;i<576*64;i+=nt){
        int k=i>>6, o=i&63, c=k&63, tap=k>>6;
        g_wdctf2[i] = f2tf32(w_dc[(o*64+c)*9+tap]);
    }
    for (int i=t;i<4*4096;i+=nt){
        int q=i>>12, rem=i&4095, cc=rem>>9, kc=(rem>>6)&7, o=rem&63;
        g_wr1tf[i] = f2tf32(w_r1[(q*64+o)*64 + cc*8+kc]);
    }
    for (int i=t;i<32*4608;i+=nt){
        int cc=i/4608, rem=i%4608, tap=rem>>9, kc=(rem>>6)&7, o=rem&63;
        g_wr2Tf[i] = f2tf32(w_r2[(o*256 + cc*8 + kc)*9 + tap]);
    }
    for (int i=t;i<64*32;i+=nt){ int o=i%32; int c=i/32; g_wn1T[i]=w_n1[o*64+c]; }
    for (int i=t;i<32*64;i+=nt){ int o=i%64; int c=i/64; g_wn3T[i]=w_n3[o*32+c]; }
}

// ---------------- x -> tf32 bits copy ----------------------------------------
__global__ void k_cvtx(const float* __restrict__ x){
    int nt = gridDim.x*blockDim.x;
    const float4* src = (const float4*)x;
    uint4* dst = (uint4*)g_xtf;
    const int NV = BB*CCH*HWSZ/4;          // 2,359,296 uint4
    for (int i = blockIdx.x*blockDim.x + threadIdx.x; i < NV; i += nt){
        float4 v = src[i];
        dst[i] = make_uint4(f2tf32(v.x), f2tf32(v.y), f2tf32(v.z), f2tf32(v.w));
    }
}

// ---------------- offset conv 3x3 64->27 via MMA -----------------------------
#define ASX 200
#define BSO 40
__global__ __launch_bounds__(128,4) void k_off_mma(const float* __restrict__ b_off){
    __shared__ __align__(16) u32 As[3*8*ASX];   // [ri][kc][200]
    __shared__ __align__(16) u32 Bs[9*8*BSO];   // [tap][kc][40]
    int blk = blockIdx.x;
    int b = blk / HH, r = blk % HH;
    int tid = threadIdx.x;
    int wm = tid >> 5, lane = tid & 31;
    int lg = lane >> 2, lt = lane & 3;

    float c[3][4][4];
    #pragma unroll
    for (int mf=0;mf<3;mf++)
        #pragma unroll
        for (int nf=0;nf<4;nf++)
            #pragma unroll
            for (int q=0;q<4;q++) c[mf][nf][q]=0.f;

    for (int cc=0; cc<8; cc++){
        if (tid < 48){ int rc = tid>>1, side = tid&1;
            As[rc*ASX + 3 + side*193] = 0u; }
        #pragma unroll
        for (int j=0;j<9;j++){
            int i = tid + 128*j;                  // < 1152
            int rc = i/48, q = i - rc*48;
            int ri = rc>>3, kc = rc&7;
            int gr = r - 1 + ri;
            uint4 v = make_uint4(0u,0u,0u,0u);
            if (gr>=0 && gr<HH)
                v = *(const uint4*)(&g_xtf[((size_t)(b*64 + cc*8 + kc))*HWSZ + gr*WWD + 4*q]);
            *(uint4*)&As[rc*ASX + 4 + 4*q] = v;
        }
        #pragma unroll
        for (int j=0;j<5;j++){
            int i = tid + 128*j;
            if (i < 576){
                int wd = 4*i;
                int tap = wd>>8, rem = wd&255, kc = rem>>5, o = rem&31;
                *(uint4*)&Bs[(tap*8+kc)*BSO + o] = *(const uint4*)&g_wofftf[cc*2304 + wd];
            }
        }
        __syncthreads();
        #pragma unroll
        for (int tap=0; tap<9; tap++){
            int dh = tap/3, dw = tap%3;
            u32 a[3][4];
            #pragma unroll
            for (int mf=0;mf<3;mf++){
                int p0 = wm*48 + mf*16 + lg;
                int col0 = p0 + dw + 3;
                const u32* alo = &As[(dh*8+lt  )*ASX];
                const u32* ahi = &As[(dh*8+lt+4)*ASX];
                a[mf][0]=alo[col0]; a[mf][1]=alo[col0+8];
                a[mf][2]=ahi[col0]; a[mf][3]=ahi[col0+8];
            }
            u32 bb[4][2];
            #pragma unroll
            for (int nf=0;nf<4;nf++){
                int n = nf*8 + lg;
                bb[nf][0] = Bs[(tap*8+lt  )*BSO + n];
                bb[nf][1] = Bs[(tap*8+lt+4)*BSO + n];
            }
            #pragma unroll
            for (int mf=0;mf<3;mf++)
                #pragma unroll
                for (int nf=0;nf<4;nf++)
                    MMA_TF32(c[mf][nf], a[mf][0],a[mf][1],a[mf][2],a[mf][3], bb[nf][0],bb[nf][1]);
        }
        __syncthreads();
    }
    int rbase = r*WWD;
    #pragma unroll
    for (int mf=0;mf<3;mf++){
        int p0 = wm*48 + mf*16 + lg;
        #pragma unroll
        for (int nf=0;nf<4;nf++){
            int o0 = nf*8 + 2*lt;
            #pragma unroll
            for (int q=0;q<4;q++){
                int o = o0 + (q&1);
                int p = p0 + (q>>1)*8;
                if (o < 27){
                    float v = leakyf(c[mf][nf][q] + b_off[o]);
                    if (o < 18) g_off [(b*18+o)*HWSZ + rbase + p] = v;
                    else        g_mask[(b*9+(o-18))*HWSZ + rbase + p] = sigmf(v);
                }
            }
        }
    }
}

// ---------------- deform sampler (monolithic) --------------------------------
__global__ __launch_bounds__(192,8) void k_dsample(const float* __restrict__ x){
    int b = blockIdx.x / HH, r = blockIdx.x % HH;
    int tap = blockIdx.y;
    int px = threadIdx.x;
    int hw = r*WWD + px;

    float dy = g_off[(b*18+2*tap  )*HWSZ+hw];
    float dx = g_off[(b*18+2*tap+1)*HWSZ+hw];
    float m  = g_mask[(b*9+tap)*HWSZ+hw];
    float py = (float)r  + (float)(tap/3-1) + dy;
    float pxf= (float)px + (float)(tap%3-1) + dx;
    float y0f = floorf(py), x0f = floorf(pxf);
    float wy = py - y0f,  wx = pxf - x0f;
    int y0=(int)y0f, x0=(int)x0f, y1=y0+1, x1=x0+1;
    bool vy0=(y0>=0&&y0<HH), vy1=(y1>=0&&y1<HH);
    bool vx0=(x0>=0&&x0<WWD), vx1=(x1>=0&&x1<WWD);
    float w00=(1.f-wy)*(1.f-wx)*((vy0&&vx0)?m:0.f);
    float w01=(1.f-wy)*wx      *((vy0&&vx1)?m:0.f);
    float w10=wy*(1.f-wx)      *((vy1&&vx0)?m:0.f);
    float w11=wy*wx            *((vy1&&vx1)?m:0.f);
    int cy0=min(max(y0,0),HH-1), cy1=min(max(y1,0),HH-1);
    int cx0=min(max(x0,0),WWD-1), cx1=min(max(x1,0),WWD-1);
    int i00=cy0*WWD+cx0, i01=cy0*WWD+cx1, i10=cy1*WWD+cx0, i11=cy1*WWD+cx1;

    const float* xb = x + (size_t)b*64*HWSZ;
    u32* dst = g_ds + (size_t)(b*576 + tap*64)*HWSZ + hw;
    #pragma unroll 8
    for (int c=0;c<64;c++){
        const float* xc = xb + (size_t)c*HWSZ;
        float v = w00*xc[i00] + w01*xc[i01] + w10*xc[i10] + w11*xc[i11];
        dst[(size_t)c*HWSZ] = f2tf32(v);
    }
}

// ---------------- dc GEMM: 576 -> 64, cp.async double-buffered ---------------
__global__ __launch_bounds__(256,2) void k_dc_gemm(const float* __restrict__ b_dc){
    __shared__ __align__(16) u32 As[2][16*ASX];   // 25.6KB
    __shared__ __align__(16) u32 Bs[2][16*72];    // 9.2KB
    int b = blockIdx.x / HH, r = blockIdx.x % HH;
    int tid = threadIdx.x;
    int w  = tid >> 5, lane = tid & 31;
    int wm = w & 3, wn = w >> 2;
    int lg = lane >> 2, lt = lane & 3;

    const int ASZ = 16*ASX, BSZ = 16*72;
    u32 as_base = (u32)__cvta_generic_to_shared(&As[0][0]);
    u32 bs_base = (u32)__cvta_generic_to_shared(&Bs[0][0]);
    const u32* dsb = g_ds + (size_t)b*576*HWSZ + r*WWD;

    float c[3][4][4];
    #pragma unroll
    for (int mf=0;mf<3;mf++)
        #pragma unroll
        for (int nf=0;nf<4;nf++)
            #pragma unroll
            for (int q=0;q<4;q++) c[mf][nf][q]=0.f;

    auto stage = [&](int ch, int bi){
        #pragma unroll
        for (int j=0;j<3;j++){
            int i = tid + 256*j;                  // < 768
            int kc = i/48, q = i - kc*48;
            cp16(as_base + (u32)(bi*ASZ + kc*ASX + 4*q)*4u,
                 &dsb[(size_t)(ch*16 + kc)*HWSZ + 4*q], 16);
        }
        {
            int wd = 4*tid;                       // < 1024
            int kc = wd>>6, o = wd&63;
            cp16(bs_base + (u32)(bi*BSZ + kc*72 + o)*4u,
                 &g_wdctf2[ch*1024 + wd], 16);
        }
        cp_commit();
    };

    stage(0, 0);
    for (int ch=0; ch<36; ch++){
        int bi = ch & 1;
        if (ch < 35){ stage(ch+1, bi^1); cp_wait<1>(); }
        else        { cp_wait<0>(); }
        __syncthreads();
        #pragma unroll
        for (int ks=0; ks<2; ks++){
            u32 a[3][4];
            #pragma unroll
            for (int mf=0;mf<3;mf++){
                int p0 = wm*48 + mf*16 + lg;
                const u32* alo = &As[bi][(ks*8+lt  )*ASX];
                const u32* ahi = &As[bi][(ks*8+lt+4)*ASX];
                a[mf][0]=alo[p0]; a[mf][1]=alo[p0+8];
                a[mf][2]=ahi[p0]; a[mf][3]=ahi[p0+8];
            }
            u32 bb[4][2];
            #pragma unroll
            for (int nf=0;nf<4;nf++){
                int n = wn*32 + nf*8 + lg;
                bb[nf][0] = Bs[bi][(ks*8+lt  )*72 + n];
                bb[nf][1] = Bs[bi][(ks*8+lt+4)*72 + n];
            }
            #pragma unroll
            for (int mf=0;mf<3;mf++)
                #pragma unroll
                for (int nf=0;nf<4;nf++)
                    MMA_TF32(c[mf][nf], a[mf][0],a[mf][1],a[mf][2],a[mf][3], bb[nf][0],bb[nf][1]);
        }
        __syncthreads();
    }
    float* xdb = g_xd + (size_t)b*64*HWSZ + r*WWD;
    #pragma unroll
    for (int mf=0;mf<3;mf++){
        int p0 = wm*48 + mf*16 + lg;
        #pragma unroll
        for (int nf=0;nf<4;nf++){
            int o0 = wn*32 + nf*8 + 2*lt;
            float bz0 = b_dc[o0], bz1 = b_dc[o0+1];
            xdb[(size_t)o0    *HWSZ + p0    ] = c[mf][nf][0] + bz0;
            xdb[(size_t)(o0+1)*HWSZ + p0    ] = c[mf][nf][1] + bz1;
            xdb[(size_t)o0    *HWSZ + p0 + 8] = c[mf][nf][2] + bz0;
            xdb[(size_t)(o0+1)*HWSZ + p0 + 8] = c[mf][nf][3] + bz1;
        }
    }
}

// ---------------- channel-attention mean reduce ------------------------------
__global__ void k_ca_red(){
    int bc = blockIdx.x;
    const float4* src = (const float4*)(g_xd + (size_t)bc*HWSZ);
    float s = 0.f;
    for (int i=threadIdx.x;i<HWSZ/4;i+=blockDim.x){
        float4 v = src[i]; s += (v.x+v.y)+(v.z+v.w);
    }
    __shared__ float red[256];
    red[threadIdx.x]=s; __syncthreads();
    for (int st=128;st>0;st>>=1){ if (threadIdx.x<st) red[threadIdx.x]+=red[threadIdx.x+st]; __syncthreads(); }
    if (threadIdx.x==0) g_camean[bc] = red[0]*(1.f/(float)HWSZ);
}

// ---------------- channel-attention MLP --------------------------------------
__global__ void k_ca_mlp(const float* __restrict__ w_ca1, const float* __restrict__ b_ca1,
                         const float* __restrict__ w_ca2, const float* __restrict__ b_ca2){
    __shared__ float hid[4*8];
    int t = threadIdx.x;
    if (t<32){ int b=t/8, j=t%8;
        float s = b_ca1[j];
        for (int c=0;c<64;c++) s += w_ca1[j*64+c]*g_camean[b*64+c];
        hid[b*8+j] = fmaxf(s,0.f);
    }
    __syncthreads();
    if (t<256){ int b=t/64, o=t%64;
        float s = b_ca2[o];
        #pragma unroll
        for (int j=0;j<8;j++) s += w_ca2[o*8+j]*hid[b*8+j];
        g_ca[t] = sigmf(s);
    }
}

// ---------------- sa pass 1: u_k[p] = sum_c W[c,k]*xd[c,p]  ------------------
__global__ void k_sa1(const float* __restrict__ w_sa){
    __shared__ float sW[64*9];
    for (int j=threadIdx.x;j<576;j+=blockDim.x) sW[j]=w_sa[j];
    __syncthreads();
    int p = blockIdx.x*blockDim.x + threadIdx.x;
    if (p>=NPIX) return;
    int b=p/HWSZ, hw=p%HWSZ;
    float u[9];
    #pragma unroll
    for (int k=0;k<9;k++) u[k]=0.f;
    const float* xb = g_xd + (size_t)b*64*HWSZ + hw;
    for (int c=0;c<64;c++){
        float v = xb[(size_t)c*HWSZ];
        #pragma unroll
        for (int k=0;k<9;k++) u[k] += v*sW[c*9+k];
    }
    #pragma unroll
    for (int k=0;k<9;k++) g_sau[(b*9+k)*HWSZ+hw] = u[k];
}

// ---------------- sa pass 2: shift-add 9 planes, sigmoid, xa=xd*(ca+sa) ------
__global__ void k_sa_xa2(const float* __restrict__ b_sa){
    int p = blockIdx.x*blockDim.x + threadIdx.x;
    if (p>=NPIX) return;
    int b=p/HWSZ, hw=p%HWSZ, h=hw/WWD, w=hw%WWD;
    float s = b_sa[0];
    #pragma unroll
    for (int k=0;k<9;k++){
        int hy=h+k/3-1, wx=w+k%3-1;
        if (hy>=0 && hy<HH && wx>=0 && wx<WWD)
            s += g_sau[(b*9+k)*HWSZ + hy*WWD+wx];
    }
    s = sigmf(s);
    const float* xb = g_xd + (size_t)b*64*HWSZ + hw;
    u32* ob = g_xatf + (size_t)b*64*HWSZ + hw;
    for (int c=0;c<64;c++){
        float scale = g_ca[b*64+c] + s;
        ob[(size_t)c*HWSZ] = f2tf32(xb[(size_t)c*HWSZ]*scale);
    }
}

// ---------------- r1: conv1x1 64->256 via MMA, leaky, store tf32 -------------
__global__ __launch_bounds__(256,2) void k_r1_mma(const float* __restrict__ b_r1){
    __shared__ __align__(16) u32 As[8*ASX];     // 6.4KB
    __shared__ __align__(16) u32 Bs[8*72];      // 2.3KB
    int blk = blockIdx.x;
    int b = blk / HH, r = blk % HH;
    int oc0 = blockIdx.y*64;
    int tid = threadIdx.x;
    int w  = tid >> 5, lane = tid & 31;
    int wm = w & 3, wn = w >> 2;
    int lg = lane >> 2, lt = lane & 3;

    float c[3][4][4];
    #pragma unroll
    for (int mf=0;mf<3;mf++)
        #pragma unroll
        for (int nf=0;nf<4;nf++)
            #pragma unroll
            for (int q=0;q<4;q++) c[mf][nf][q]=0.f;

    for (int cc=0; cc<8; cc++){
        #pragma unroll
        for (int j=0;j<2;j++){
            int i = tid + 256*j;
            if (i < 384){
                int kc = i/48, q = i - kc*48;
                *(uint4*)&As[kc*ASX + 4*q] =
                    *(const uint4*)&g_xatf[((size_t)(b*64 + cc*8 + kc))*HWSZ + r*WWD + 4*q];
            }
        }
        if (tid < 128){
            int wd = 4*tid;
            int kc = wd>>6, o = wd&63;
            *(uint4*)&Bs[kc*72 + o] = *(const uint4*)&g_wr1tf[blockIdx.y*4096 + cc*512 + wd];
        }
        __syncthreads();
        u32 a[3][4];
        #pragma unroll
        for (int mf=0;mf<3;mf++){
            int p0 = wm*48 + mf*16 + lg;
            const u32* alo = &As[lt*ASX];
            const u32* ahi = &As[(lt+4)*ASX];
            a[mf][0]=alo[p0]; a[mf][1]=alo[p0+8];
            a[mf][2]=ahi[p0]; a[mf][3]=ahi[p0+8];
        }
        u32 bb[4][2];
        #pragma unroll
        for (int nf=0;nf<4;nf++){
            int n = wn*32 + nf*8 + lg;
            bb[nf][0] = Bs[lt*72 + n];
            bb[nf][1] = Bs[(lt+4)*72 + n];
        }
        #pragma unroll
        for (int mf=0;mf<3;mf++)
            #pragma unroll
            for (int nf=0;nf<4;nf++)
                MMA_TF32(c[mf][nf], a[mf][0],a[mf][1],a[mf][2],a[mf][3], bb[nf][0],bb[nf][1]);
        __syncthreads();
    }
    float* ob = g_r1 + ((size_t)b*256+oc0)*HWSZ + r*WWD;
    #pragma unroll
    for (int mf=0;mf<3;mf++){
        int p0 = wm*48 + mf*16 + lg;
        #pragma unroll
        for (int nf=0;nf<4;nf++){
            int o0 = wn*32 + nf*8 + 2*lt;
            float bz0 = b_r1[oc0+o0], bz1 = b_r1[oc0+o0+1];
            ob[(size_t)o0    *HWSZ + p0    ] = __uint_as_float(f2tf32(leakyf(c[mf][nf][0] + bz0)));
            ob[(size_t)(o0+1)*HWSZ + p0    ] = __uint_as_float(f2tf32(leakyf(c[mf][nf][1] + bz1)));
            ob[(size_t)o0    *HWSZ + p0 + 8] = __uint_as_float(f2tf32(leakyf(c[mf][nf][2] + bz0)));
            ob[(size_t)(o0+1)*HWSZ + p0 + 8] = __uint_as_float(f2tf32(leakyf(c[mf][nf][3] + bz1)));
        }
    }
}

// ---------------- r2: conv3x3 256->64, cp.async double-buffered --------------
#define AS2 200
#define BS2 72
__global__ __launch_bounds__(256,2) void k_r2_mma(const float* __restrict__ b_r2){
    __shared__ __align__(16) u32 As[2][3*8*AS2];   // 38.4KB
    __shared__ __align__(16) u32 Bs[2][9*8*BS2];   // 41.5KB
    int blk = blockIdx.x;
    int b = blk / HH, r = blk % HH;
    int tid = threadIdx.x;
    int w  = tid >> 5, lane = tid & 31;
    int wm = w & 3, wn = w >> 2;
    int lg = lane >> 2, lt = lane & 3;

    const int ASZ = 3*8*AS2, BSZ = 9*8*BS2;
    u32 as_base = (u32)__cvta_generic_to_shared(&As[0][0]);
    u32 bs_base = (u32)__cvta_generic_to_shared(&Bs[0][0]);

    // zero halo columns once per buffer (cols 3 and 196; never touched by cp.async)
    if (tid < 96){ int bi = tid/48, rem = tid%48, rc = rem>>1, side = rem&1;
        As[bi][rc*AS2 + 3 + side*193] = 0u; }

    float c[3][4][4];
    #pragma unroll
    for (int mf=0;mf<3;mf++)
        #pragma unroll
        for (int nf=0;nf<4;nf++)
            #pragma unroll
            for (int q=0;q<4;q++) c[mf][nf][q]=0.f;

    auto stage = [&](int cc, int bi){
        #pragma unroll
        for (int j=0;j<5;j++){
            int i = tid + 256*j;
            if (i < 1152){
                int rc = i/48, q = i - rc*48;
                int ri = rc>>3, kc = rc&7;
                int gr = r - 1 + ri;
                int ok = (gr>=0 && gr<HH) ? 16 : 0;
                int grc = min(max(gr,0),HH-1);
                cp16(as_base + (u32)(bi*ASZ + rc*AS2 + 4 + 4*q)*4u,
                     &g_r1[((size_t)(b*256 + cc*8 + kc))*HWSZ + grc*WWD + 4*q], ok);
            }
        }
        #pragma unroll
        for (int j=0;j<5;j++){
            int i = tid + 256*j;
            if (i < 1152){
                int wd = 4*i;
                int tap = wd>>9, rem = wd&511, kc = rem>>6, o = rem&63;
                cp16(bs_base + (u32)(bi*BSZ + (tap*8+kc)*BS2 + o)*4u,
                     &g_wr2Tf[cc*4608 + wd], 16);
            }
        }
        cp_commit();
    };

    stage(0, 0);
    for (int cc=0; cc<32; cc++){
        int bi = cc & 1;
        if (cc < 31){ stage(cc+1, bi^1); cp_wait<1>(); }
        else        { cp_wait<0>(); }
        __syncthreads();
        #pragma unroll
        for (int tap=0; tap<9; tap++){
            int dh = tap/3, dw = tap%3;
            u32 a[3][4];
            #pragma unroll
            for (int mf=0;mf<3;mf++){
                int p0 = wm*48 + mf*16 + lg;
                int col0 = p0 + dw + 3;
                const u32* alo = &As[bi][(dh*8+lt  )*AS2];
                const u32* ahi = &As[bi][(dh*8+lt+4)*AS2];
                a[mf][0]=alo[col0]; a[mf][1]=alo[col0+8];
                a[mf][2]=ahi[col0]; a[mf][3]=ahi[col0+8];
            }
            u32 bb[4][2];
            #pragma unroll
            for (int nf=0;nf<4;nf++){
                int n = wn*32 + nf*8 + lg;
                bb[nf][0] = Bs[bi][(tap*8+lt  )*BS2 + n];
                bb[nf][1] = Bs[bi][(tap*8+lt+4)*BS2 + n];
            }
            #pragma unroll
            for (int mf=0;mf<3;mf++)
                #pragma unroll
                for (int nf=0;nf<4;nf++)
                    MMA_TF32(c[mf][nf], a[mf][0],a[mf][1],a[mf][2],a[mf][3], bb[nf][0],bb[nf][1]);
        }
        __syncthreads();
    }
    float* xrb = g_xr + (size_t)b*64*HWSZ + r*WWD;
    #pragma unroll
    for (int mf=0;mf<3;mf++){
        int p0 = wm*48 + mf*16 + lg;
        #pragma unroll
        for (int nf=0;nf<4;nf++){
            int o0 = wn*32 + nf*8 + 2*lt;
            float bz0 = b_r2[o0], bz1 = b_r2[o0+1];
            xrb[(size_t)o0    *HWSZ + p0    ] = c[mf][nf][0] + bz0;
            xrb[(size_t)(o0+1)*HWSZ + p0    ] = c[mf][nf][1] + bz1;
            xrb[(size_t)o0    *HWSZ + p0 + 8] = c[mf][nf][2] + bz0;
            xrb[(size_t)(o0+1)*HWSZ + p0 + 8] = c[mf][nf][3] + bz1;
        }
    }
}

// ---------------- n1: conv1x1 64->32 (FFMA2, reads tf32-as-float xa) ---------
__global__ void k_n1(const float* __restrict__ b_n1){
    __shared__ __align__(16) float sW[64*32];
    for (int j=threadIdx.x;j<2048;j+=blockDim.x) sW[j]=g_wn1T[j];
    __syncthreads();
    int p = blockIdx.x*blockDim.x + threadIdx.x;
    if (p>=NPIX) return;
    int b=p/HWSZ, hw=p%HWSZ;
    u64 acc[16];
    #pragma unroll
    for (int j=0;j<16;j++) acc[j]=pk2(b_n1[2*j], b_n1[2*j+1]);
    const float* xb = (const float*)g_xatf + (size_t)b*64*HWSZ + hw;
    for (int c=0;c<64;c++){
        u64 vp = bcast2(xb[(size_t)c*HWSZ]);
        const ulonglong2* wp=(const ulonglong2*)&sW[c*32];
        #pragma unroll
        for (int j=0;j<8;j++){
            ulonglong2 ww=wp[j];
            ffma2(acc[2*j],   vp, ww.x);
            ffma2(acc[2*j+1], vp, ww.y);
        }
    }
    float* ob = g_n1 + (size_t)b*32*HWSZ + hw;
    #pragma unroll
    for (int j=0;j<16;j++){
        float2 f=upk(acc[j]);
        ob[(size_t)(2*j  )*HWSZ]=f.x;
        ob[(size_t)(2*j+1)*HWSZ]=f.y;
    }
}

// ---------------- n2: depthwise 3x3 (32 ch) ----------------------------------
__global__ void k_n2(const float* __restrict__ w_n2, const float* __restrict__ b_n2){
    __shared__ float sW[32*9];
    for (int j=threadIdx.x;j<288;j+=blockDim.x) sW[j]=w_n2[j];
    __syncthreads();
    int p = blockIdx.x*blockDim.x + threadIdx.x;
    if (p>=NPIX) return;
    int b=p/HWSZ, hw=p%HWSZ, h=hw/WWD, w=hw%WWD;
    int toff[9]; bool tv[9];
    #pragma unroll
    for (int k=0;k<9;k++){
        int hy=h+k/3-1, wx=w+k%3-1;
        tv[k]=(hy>=0&&hy<HH&&wx>=0&&wx<WWD);
        toff[k]=tv[k]?hy*WWD+wx:0;
    }
    const float* xb = g_n1 + (size_t)b*32*HWSZ;
    float* ob = g_n2 + (size_t)b*32*HWSZ;
    for (int c=0;c<32;c++){
        const float* xc = xb + (size_t)c*HWSZ;
        float acc = b_n2[c];
        #pragma unroll
        for (int k=0;k<9;k++) if (tv[k]) acc += xc[toff[k]]*sW[c*9+k];
        ob[(size_t)c*HWSZ+hw]=acc;
    }
}

// ---------------- final: conv1x1 32->64 + x + xr -> out ----------------------
__global__ void k_final(const float* __restrict__ x, const float* __restrict__ b_n3,
                        float* __restrict__ out){
    __shared__ __align__(16) float sW[32*64];
    for (int j=threadIdx.x;j<2048;j+=blockDim.x) sW[j]=g_wn3T[j];
    __syncthreads();
    int p = blockIdx.x*blockDim.x + threadIdx.x;
    if (p>=NPIX) return;
    int b=p/HWSZ, hw=p%HWSZ;
    u64 acc[32];
    #pragma unroll
    for (int j=0;j<32;j++) acc[j]=pk2(b_n3[2*j], b_n3[2*j+1]);
    const float* xb = g_n2 + (size_t)b*32*HWSZ + hw;
    for (int c=0;c<32;c++){
        u64 vp = bcast2(xb[(size_t)c*HWSZ]);
        const ulonglong2* wp=(const ulonglong2*)&sW[c*64];
        #pragma unroll
        for (int j=0;j<16;j++){
            ulonglong2 ww=wp[j];
            ffma2(acc[2*j],   vp, ww.x);
            ffma2(acc[2*j+1], vp, ww.y);
        }
    }
    const float* xin = x + (size_t)b*64*HWSZ + hw;
    const float* xr  = g_xr + (size_t)b*64*HWSZ + hw;
    float* ob = out + (size_t)b*64*HWSZ + hw;
    #pragma unroll
    for (int j=0;j<32;j++){
        float2 f=upk(acc[j]);
        ob[(size_t)(2*j  )*HWSZ] = xin[(size_t)(2*j  )*HWSZ] + xr[(size_t)(2*j  )*HWSZ] + f.x;
        ob[(size_t)(2*j+1)*HWSZ] = xin[(size_t)(2*j+1)*HWSZ] + xr[(size_t)(2*j+1)*HWSZ] + f.y;
    }
}

// ---------------- launch ------------------------------------------------------
extern "C" void kernel_launch(void* const* d_in, const int* in_sizes, int n_in,
                              void* d_out, int out_size){
    const float* x     = (const float*)d_in[0];
    const float* w_off = (const float*)d_in[1];
    const float* b_off = (const float*)d_in[2];
    const float* w_dc  = (const float*)d_in[3];
    const float* b_dc  = (const float*)d_in[4];
    const float* w_ca1 = (const float*)d_in[5];
    const float* b_ca1 = (const float*)d_in[6];
    const float* w_ca2 = (const float*)d_in[7];
    const float* b_ca2 = (const float*)d_in[8];
    const float* w_sa  = (const float*)d_in[9];
    const float* b_sa  = (const float*)d_in[10];
    const float* w_r1  = (const float*)d_in[11];
    const float* b_r1  = (const float*)d_in[12];
    const float* w_r2  = (const float*)d_in[13];
    const float* b_r2  = (const float*)d_in[14];
    const float* w_n1  = (const float*)d_in[15];
    const float* b_n1  = (const float*)d_in[16];
    const float* w_n2  = (const float*)d_in[17];
    const float* b_n2  = (const float*)d_in[18];
    const float* w_n3  = (const float*)d_in[19];
    const float* b_n3  = (const float*)d_in[20];
    float* out = (float*)d_out;

    const int TPB = 256;
    const int GP  = (NPIX + TPB - 1)/TPB;   // 576
    const int GR  = BB*HH;                  // 768 row-blocks

    k_prep<<<64, 256>>>(w_off, w_dc, w_r1, w_r2, w_n1, w_n3);
    k_cvtx<<<GP, TPB>>>(x);
    k_off_mma<<<GR, 128>>>(b_off);
    k_dsample<<<dim3(GR, 9), 192>>>(x);
    k_dc_gemm<<<GR, TPB>>>(b_dc);
    k_ca_red<<<BB*CCH, 256>>>();
    k_ca_mlp<<<1, 256>>>(w_ca1, b_ca1, w_ca2, b_ca2);
    k_sa1<<<GP, TPB>>>(w_sa);
    k_sa_xa2<<<GP, TPB>>>(b_sa);
    k_r1_mma<<<dim3(GR,4), TPB>>>(b_r1);
    k_r2_mma<<<GR, TPB>>>(b_r2);
    k_n1<<<GP, TPB>>>(b_n1);
    k_n2<<<GP, TPB>>>(w_n2, b_n2);
    k_final<<<GP, TPB>>>(x, b_n3, out);
}